// round 14
// baseline (speedup 1.0000x reference)
#include <cuda_runtime.h>
#include <math.h>

// ---------------- f32x2 packed-FMA helpers (bitwise = 2x IEEE fp32 FMA) ----
__device__ __forceinline__ unsigned long long f2pack(float x,float y){
  unsigned long long r;
  asm("mov.b64 %0,{%1,%2};":"=l"(r):"r"(__float_as_uint(x)),"r"(__float_as_uint(y)));
  return r;
}
__device__ __forceinline__ void f2unpack(unsigned long long v,float&x,float&y){
  unsigned ux,uy;
  asm("mov.b64 {%0,%1},%2;":"=r"(ux),"=r"(uy):"l"(v));
  x=__uint_as_float(ux); y=__uint_as_float(uy);
}
__device__ __forceinline__ void ffma2(unsigned long long&d,unsigned long long a,unsigned long long b){
  asm("fma.rn.f32x2 %0,%1,%2,%0;":"+l"(d):"l"(a),"l"(b));
}

// ---------------- scratch ----------------
__device__ float g_SESS[128*128];
__device__ int   g_IN1[128*400];
__device__ float g_W0 [128*400];
__device__ int   g_IN2[128*3200];
__device__ float g_W1n[128*3200];
__device__ float g_NG0[128*50*128];
__device__ float g_NG1[128*400*128];
__device__ float g_A0 [128*50*128];
__device__ float g_A1 [128*400*128];
__device__ float g_HL [128*50*128];
__device__ float g_HG [128*50*128];
__device__ float g_NH [128*50*128];
__device__ float g_SEL[128*128];
__device__ float g_SEL2T[128*128];
__device__ float g_LP[128];
__device__ int   g_PR[128];
__device__ int   g_PC[64];

// ---------------- threefry ----------------
__device__ __forceinline__ void tf(unsigned k0,unsigned k1,unsigned x0,unsigned x1,
                                   unsigned&o0,unsigned&o1){
  unsigned ks2=k0^k1^0x1BD11BDAu;
  x0+=k0; x1+=k1;
#define RND(r) {x0+=x1; x1=(x1<<(r))|(x1>>(32-(r))); x1^=x0;}
  RND(13)RND(15)RND(26)RND(6)   x0+=k1;  x1+=ks2+1u;
  RND(17)RND(29)RND(16)RND(24)  x0+=ks2; x1+=k0+2u;
  RND(13)RND(15)RND(26)RND(6)   x0+=k0;  x1+=k1+3u;
  RND(17)RND(29)RND(16)RND(24)  x0+=k1;  x1+=ks2+4u;
  RND(13)RND(15)RND(26)RND(6)   x0+=ks2; x1+=k0+5u;
#undef RND
  o0=x0; o1=x1;
}

__global__ void k_perm(){
  __shared__ unsigned keys[4];
  __shared__ unsigned br[128];
  __shared__ unsigned bc[64];
  int t=threadIdx.x;
  if(t==0){
    unsigned u0,u1,v0,v1,p0,p1,q0,q1;
    tf(0u,42u,0u,2u,u0,u1); tf(0u,42u,1u,3u,v0,v1);
    unsigned kr0=u0,kr1=v0,kc0=u1,kc1=v1;
    tf(kr0,kr1,0u,2u,p0,p1); tf(kr0,kr1,1u,3u,q0,q1);
    keys[0]=p1; keys[1]=q1;
    tf(kc0,kc1,0u,2u,p0,p1); tf(kc0,kc1,1u,3u,q0,q1);
    keys[2]=p1; keys[3]=q1;
  }
  __syncthreads();
  { int j=t&63; unsigned w0,w1;
    tf(keys[0],keys[1],(unsigned)j,(unsigned)(j+64),w0,w1);
    br[t]=(t<64)?w0:w1; }
  if(t<50){ int j=(t<25)?t:t-25; unsigned w0,w1;
    tf(keys[2],keys[3],(unsigned)j,(unsigned)(j+25),w0,w1);
    bc[t]=(t<25)?w0:w1; }
  __syncthreads();
  { unsigned mine=br[t]; int r=0;
    for(int j=0;j<128;j++){ unsigned bj=br[j]; r+=(bj<mine)||(bj==mine&&j<t); }
    g_PR[r]=t; }
  if(t<50){ unsigned mine=bc[t]; int r=0;
    for(int j=0;j<50;j++){ unsigned bj=bc[j]; r+=(bj<mine)||(bj==mine&&j<t); }
    g_PC[r]=t; }
}

// ---------------- prep ----------------
__global__ void k_prep1(const int* __restrict__ inputs,const int* __restrict__ adj_all,
                        const float* __restrict__ num_w){
  int t=blockIdx.x*blockDim.x+threadIdx.x;
  if(t<128*400){
    int b=t/400,m=t%400;
    int node=inputs[b*50+(m>>3)];
    g_IN1[t]=adj_all[node*8+(m&7)];
    g_W0[t]=num_w[node*8+(m&7)];
  }
}
__global__ void k_prep2(const int* __restrict__ adj_all,const float* __restrict__ num_w){
  int t=blockIdx.x*blockDim.x+threadIdx.x;
  if(t<128*3200){
    int b=t/3200,m=t%3200;
    int node=g_IN1[b*400+(m>>3)];
    g_IN2[t]=adj_all[node*8+(m&7)];
    g_W1n[t]=num_w[node*8+(m&7)];
  }
}
__global__ void k_sess(const int* __restrict__ item,const int* __restrict__ mask,
                       const float* __restrict__ emb){
  int b=blockIdx.x,d=threadIdx.x;
  float acc=0.f,ms=0.f;
  for(int l=0;l<50;l++){
    float mv=(float)mask[b*50+l];
    acc+=emb[(size_t)item[b*50+l]*128+d]*mv; ms+=mv;
  }
  g_SESS[b*128+d]=acc/ms;
}

// ---------------- local agg ----------------
__global__ void __launch_bounds__(256) k_local(const int* __restrict__ inputs,
    const int* __restrict__ adj,const float* __restrict__ emb,
    const float* __restrict__ a_local){
  __shared__ float hs[6400];
  __shared__ float al[512];
  __shared__ float hik[512];
  __shared__ float es[50];
  __shared__ float att[50];
  int b=blockIdx.x,t=threadIdx.x,warp=t>>5,lane=t&31;
  for(int i=t;i<6400;i+=256) hs[i]=emb[(size_t)inputs[b*50+(i>>7)]*128+(i&127)];
  for(int i=t;i<512;i+=256) al[i]=a_local[i];
  __syncthreads();
  for(int ii=0;ii<50;ii++){
    if(t<128){
      float hv=hs[ii*128+t];
      #pragma unroll
      for(int k=0;k<4;k++) hik[k*128+t]=hv*al[k*128+t];
    }
    __syncthreads();
    for(int jj=warp;jj<50;jj+=8){
      int aj=adj[b*2500+ii*50+jj];
      int k=aj>0?aj-1:0;
      const float4* hk=(const float4*)(hik+k*128);
      const float4* hj=(const float4*)(hs+jj*128);
      float4 p=hk[lane],q=hj[lane];
      float v=p.x*q.x+p.y*q.y+p.z*q.z+p.w*q.w;
      for(int o=16;o;o>>=1) v+=__shfl_xor_sync(0xffffffffu,v,o);
      float e=(aj>0)?(v>0.f?v:0.2f*v):-9e15f;
      if(lane==0) es[jj]=e;
    }
    __syncthreads();
    if(warp==0){
      float m1=-3.4e38f;
      for(int j=lane;j<50;j+=32) m1=fmaxf(m1,es[j]);
      for(int o=16;o;o>>=1) m1=fmaxf(m1,__shfl_xor_sync(0xffffffffu,m1,o));
      float ss=0.f;
      for(int j=lane;j<50;j+=32){ float ex=expf(es[j]-m1); att[j]=ex; ss+=ex; }
      for(int o=16;o;o>>=1) ss+=__shfl_xor_sync(0xffffffffu,ss,o);
      float inv=1.f/ss;
      for(int j=lane;j<50;j+=32) att[j]*=inv;
    }
    __syncthreads();
    if(t<128){
      float acc=0.f;
      for(int j=0;j<50;j++) acc+=att[j]*hs[j*128+t];
      g_HL[(size_t)b*6400+ii*128+t]=acc;
    }
    __syncthreads();
  }
}

// ===== attention core: warp w <-> row m0+w, all 8 samples warp-local =======
// nw values staged through warp-private smem (no global load in epilogue).
// Arithmetic chains bitwise-identical to R12.
#define ATT_COMPUTE(OUTNG,MTOT)                                                \
  {                                                                            \
    __syncwarp();                                                              \
    unsigned long long acc2[8][2];                                             \
    _Pragma("unroll")                                                          \
    for(int ss=0;ss<8;ss++){ acc2[ss][0]=0ull; acc2[ss][1]=0ull; }             \
    for(int e4=0;e4<32;e4++){                                                  \
      ulonglong2 w0 =WT8[(e4*4+0)*32+lane];                                    \
      ulonglong2 w1v=WT8[(e4*4+1)*32+lane];                                    \
      ulonglong2 w2v=WT8[(e4*4+2)*32+lane];                                    \
      ulonglong2 w3v=WT8[(e4*4+3)*32+lane];                                    \
      _Pragma("unroll")                                                        \
      for(int ss=0;ss<8;ss++){                                                 \
        float4 a=NV4[(w*8+ss)*32+e4];                                          \
        unsigned long long ax=f2pack(a.x,a.x);                                 \
        unsigned long long ay=f2pack(a.y,a.y);                                 \
        unsigned long long az=f2pack(a.z,a.z);                                 \
        unsigned long long aw=f2pack(a.w,a.w);                                 \
        ffma2(acc2[ss][0],ax,w0.x);  ffma2(acc2[ss][1],ax,w0.y);               \
        ffma2(acc2[ss][0],ay,w1v.x); ffma2(acc2[ss][1],ay,w1v.y);              \
        ffma2(acc2[ss][0],az,w2v.x); ffma2(acc2[ss][1],az,w2v.y);              \
        ffma2(acc2[ss][0],aw,w3v.x); ffma2(acc2[ss][1],aw,w3v.y);              \
      }                                                                        \
    }                                                                          \
    int d0=lane*4;                                                             \
    float pr[8];                                                               \
    _Pragma("unroll")                                                          \
    for(int ss=0;ss<8;ss++){                                                   \
      float a0,a1,a2,a3;                                                       \
      f2unpack(acc2[ss][0],a0,a1);                                             \
      f2unpack(acc2[ss][1],a2,a3);                                             \
      float nwv=nws[w*8+ss];                                                   \
      float v0=a0+nwv*w129[d0];                                                \
      float v1=a1+nwv*w129[d0+1];                                              \
      float v2=a2+nwv*w129[d0+2];                                              \
      float v3=a3+nwv*w129[d0+3];                                              \
      v0=v0>0.f?v0:0.2f*v0; v1=v1>0.f?v1:0.2f*v1;                              \
      v2=v2>0.f?v2:0.2f*v2; v3=v3>0.f?v3:0.2f*v3;                              \
      float p=v0*g2[d0]+v1*g2[d0+1]+v2*g2[d0+2]+v3*g2[d0+3];                   \
      for(int o=16;o;o>>=1) p+=__shfl_xor_sync(0xffffffffu,p,o);               \
      pr[ss]=p;                                                                \
    }                                                                          \
    float mx=pr[0];                                                            \
    _Pragma("unroll")                                                          \
    for(int i=1;i<8;i++) mx=fmaxf(mx,pr[i]);                                   \
    float exr[8];                                                              \
    _Pragma("unroll")                                                          \
    for(int i=0;i<8;i++) exr[i]=expf(pr[i]-mx);                                \
    float ssum=0.f;                                                            \
    _Pragma("unroll")                                                          \
    for(int i=0;i<8;i++) ssum+=exr[i];                                         \
    float inv=1.f/ssum;                                                        \
    if(m0+w<MTOT){                                                             \
      float o0=0.f,o1=0.f,o2=0.f,o3=0.f;                                       \
      _Pragma("unroll")                                                        \
      for(int i=0;i<8;i++){                                                    \
        float ali=exr[i]*inv;                                                  \
        float4 r=NV4[(w*8+i)*32+lane];                                         \
        o0+=ali*r.x; o1+=ali*r.y; o2+=ali*r.z; o3+=ali*r.w;                    \
      }                                                                        \
      float4 ov; ov.x=o0; ov.y=o1; ov.z=o2; ov.w=o3;                           \
      ((float4*)OUTNG)[((size_t)b*MTOT+(m0+w))*32+lane]=ov;                    \
    }                                                                          \
  }

// ---------------- hop-0 global attention: flattened queue ------------------
__global__ void __launch_bounds__(256) k_att2(int Q,
    const float* __restrict__ emb,const float* __restrict__ gw1h,
    const float* __restrict__ gw2h){
  extern __shared__ float sm[];
  float* wt  = sm;         // 16384 [e][d]
  float* nv  = sm+16384;   // 8192 : 64 rows of 128
  float* w129= sm+24576;   // 128
  float* g2  = sm+24704;   // 128
  float* nws = sm+24832;   // 64
  int t=threadIdx.x,lane=t&31,w=t>>5;
  if(t<128){ w129[t]=gw1h[16384+t]; g2[t]=gw2h[t]; }
  __syncthreads();
  const ulonglong2* WT8=(const ulonglong2*)wt;
  const float4* NV4=(const float4*)nv;
  int g0=blockIdx.x*Q, g1=min(g0+Q,7296);
  int cur_b=-1;
  float4 pfv[8];
  float pfw=0.f;
#define ATT2_PRE(G) do{ \
    int bb=(G)/57, cc=(G)-bb*57; \
    int is1p=(cc>=7); \
    int Mt=is1p?400:50; \
    int mm0=(is1p?(cc-7):cc)*8; \
    const int* ni=is1p?g_IN2:g_IN1; \
    const float* nwq=is1p?g_W1n:g_W0; \
    int mp=min(mm0+w,Mt-1); \
    size_t bp=((size_t)bb*Mt+mp)*8; \
    _Pragma("unroll") \
    for(int ss=0;ss<8;ss++) \
      pfv[ss]=((const float4*)emb)[(size_t)ni[bp+ss]*32+lane]; \
    if(lane<8) pfw=nwq[bp+lane]; \
  }while(0)
  if(g0<g1) ATT2_PRE(g0);
  for(int g=g0;g<g1;g++){
    int b=g/57, c=g-b*57;
    if(b!=cur_b){
      __syncthreads();
      for(int i=t;i<16384;i+=256) wt[i]=g_SESS[b*128+(i>>7)]*gw1h[i];
      cur_b=b;
      __syncthreads();
    }
    int is1=(c>=7);
    int Mtot=is1?400:50;
    int m0=(is1?(c-7):c)*8;
    float* outNG = is1?g_NG1:g_NG0;
    #pragma unroll
    for(int ss=0;ss<8;ss++)
      ((float4*)nv)[(w*8+ss)*32+lane]=pfv[ss];
    if(lane<8) nws[w*8+lane]=pfw;
    if(g+1<g1) ATT2_PRE(g+1);
    ATT_COMPUTE(outNG,Mtot)
  }
#undef ATT2_PRE
}

// ---------------- hop-1 attention (src = g_A1 rows) -------------------------
__global__ void __launch_bounds__(256) k_attm2(int Q,
    const float* __restrict__ gw1h,const float* __restrict__ gw2h){
  extern __shared__ float sm[];
  float* wt  = sm;
  float* nv  = sm+16384;
  float* w129= sm+24576;
  float* g2  = sm+24704;
  float* nws = sm+24832;
  int t=threadIdx.x,lane=t&31,w=t>>5;
  if(t<128){ w129[t]=gw1h[16384+t]; g2[t]=gw2h[t]; }
  __syncthreads();
  const ulonglong2* WT8=(const ulonglong2*)wt;
  const float4* NV4=(const float4*)nv;
  int g0=blockIdx.x*Q, g1=min(g0+Q,896);
  int cur_b=-1;
  float4 pfv[8];
  float pfw=0.f;
#define ATTM_PRE(G) do{ \
    int bb=(G)/7, cc=(G)-bb*7; \
    int mp=min(cc*8+w,49); \
    size_t bp=((size_t)bb*50+mp)*8; \
    _Pragma("unroll") \
    for(int ss=0;ss<8;ss++) \
      pfv[ss]=((const float4*)g_A1)[(bp+ss)*32+lane]; \
    if(lane<8) pfw=g_W0[bp+lane]; \
  }while(0)
  if(g0<g1) ATTM_PRE(g0);
  for(int g=g0;g<g1;g++){
    int b=g/7, c=g-b*7;
    if(b!=cur_b){
      __syncthreads();
      for(int i=t;i<16384;i+=256) wt[i]=g_SESS[b*128+(i>>7)]*gw1h[i];
      cur_b=b;
      __syncthreads();
    }
    const int Mtot=50;
    int m0=c*8;
    #pragma unroll
    for(int ss=0;ss<8;ss++)
      ((float4*)nv)[(w*8+ss)*32+lane]=pfv[ss];
    if(lane<8) nws[w*8+lane]=pfw;
    if(g+1<g1) ATTM_PRE(g+1);
    ATT_COMPUTE(g_NG0,Mtot)
  }
#undef ATTM_PRE
}

// -------- linear (concat 256 -> 128), persistent, FFMA2, double-buffered ---
// cfg2 additionally writes outmix = g_HL + relu(v)  (fused k_mix)
__global__ void __launch_bounds__(256) k_lin(int nrows,int cfg,
    const int* __restrict__ idxtab,const float* __restrict__ extA,
    const float* __restrict__ extB,const float* __restrict__ w,
    float* __restrict__ outmix){
  extern __shared__ float sm[];
  float* ws=sm;          // 32768 [e][d]
  float* inT=sm+32768;   // 8192 [e][32]
  int t=threadIdx.x;
  for(int i=t;i<32768;i+=256) ws[i]=w[i];
  int ngroups=(nrows+31)>>5;
  float* outp=(cfg==0)?g_A0:(cfg==1)?g_A1:(cfg==2)?g_HG:g_NH;
  float pf[32];
  int grp=blockIdx.x;

#define LIN_LOAD_PF(GRP) do{ \
    int row0p=(GRP)*32; \
    _Pragma("unroll") \
    for(int k=0;k<32;k++){ \
      int i=t+k*256; int r=i&31,e=i>>5,row=row0p+r; \
      float v=0.f; \
      if(row<nrows){ \
        if(e<128){ \
          if(cfg==0)      v=extA[(size_t)idxtab[row]*128+e]; \
          else if(cfg==1) v=extA[(size_t)g_IN1[row]*128+e]; \
          else if(cfg==2) v=g_A0[(size_t)row*128+e]; \
          else            v=extA[(size_t)(row%50)*128+e]; \
        }else{ \
          int e2=e-128; \
          if(cfg==0)      v=g_NG0[(size_t)row*128+e2]; \
          else if(cfg==1) v=g_NG1[(size_t)row*128+e2]; \
          else if(cfg==2) v=g_NG0[(size_t)row*128+e2]; \
          else            v=extB[(size_t)row*128+e2]; \
        } \
      } \
      pf[k]=v; \
    } \
  }while(0)

  if(grp<ngroups) LIN_LOAD_PF(grp);
  for(;grp<ngroups;grp+=gridDim.x){
    __syncthreads();
    #pragma unroll
    for(int k=0;k<32;k++) inT[t+k*256]=pf[k];
    __syncthreads();
    int nxt=grp+gridDim.x;
    if(nxt<ngroups) LIN_LOAD_PF(nxt);
    int row0=grp*32;
    int d=t&127,rh=t>>7;
    unsigned long long acc2[8];
    #pragma unroll
    for(int q=0;q<8;q++) acc2[q]=0ull;
    const ulonglong2* I8=(const ulonglong2*)inT;
    #pragma unroll 8
    for(int e=0;e<256;e++){
      float wv=ws[e*128+d];
      unsigned long long wv2=f2pack(wv,wv);
      ulonglong2 u0=I8[e*8+rh*4+0];
      ulonglong2 u1=I8[e*8+rh*4+1];
      ulonglong2 u2=I8[e*8+rh*4+2];
      ulonglong2 u3=I8[e*8+rh*4+3];
      ffma2(acc2[0],wv2,u0.x); ffma2(acc2[1],wv2,u0.y);
      ffma2(acc2[2],wv2,u1.x); ffma2(acc2[3],wv2,u1.y);
      ffma2(acc2[4],wv2,u2.x); ffma2(acc2[5],wv2,u2.y);
      ffma2(acc2[6],wv2,u3.x); ffma2(acc2[7],wv2,u3.y);
    }
    #pragma unroll
    for(int q=0;q<8;q++){
      float lo,hi;
      f2unpack(acc2[q],lo,hi);
      int rlo=row0+rh*16+q*2;
      if(rlo<nrows){
        float v=(cfg==3)?tanhf(lo):fmaxf(lo,0.f);
        outp[(size_t)rlo*128+d]=v;
        if(cfg==2) outmix[(size_t)rlo*128+d]=g_HL[(size_t)rlo*128+d]+v;
      }
      if(rlo+1<nrows){
        float v=(cfg==3)?tanhf(hi):fmaxf(hi,0.f);
        outp[(size_t)(rlo+1)*128+d]=v;
        if(cfg==2) outmix[(size_t)(rlo+1)*128+d]=g_HL[(size_t)(rlo+1)*128+d]+v;
      }
    }
  }
#undef LIN_LOAD_PF
}

// ---------------- ssl ----------------
__global__ void k_ssl(){
  __shared__ float red[128];
  int b=blockIdx.x,t=threadIdx.x;
  int pb=g_PR[b];
  float pos=0.f,neg=0.f;
  for(int l=0;l<50;l++){
    float hl=g_HL[(size_t)b*6400+l*128+t];
    float hg=g_HG[(size_t)b*6400+l*128+t];
    pos+=hl*hg;
    neg+=hg*g_HL[(size_t)pb*6400+g_PC[l]*128+t];
  }
  float sp=1.f/(1.f+expf(-pos)),sn=1.f/(1.f+expf(-neg));
  float term=-logf(1e-8f+sp)-logf(1e-8f+1.f-sn);
  red[t]=term; __syncthreads();
  for(int o=64;o;o>>=1){ if(t<o) red[t]+=red[t+o]; __syncthreads(); }
  if(t==0) g_LP[b]=red[0];
}
__global__ void k_fin(float* __restrict__ out){
  __shared__ float r[128];
  int t=threadIdx.x;
  r[t]=g_LP[t]; __syncthreads();
  for(int o=64;o;o>>=1){ if(t<o) r[t]+=r[t+o]; __syncthreads(); }
  if(t==0) out[819200]=0.005f*r[0];
}

// ---------------- glu/select ----------------
__global__ void __launch_bounds__(256) k_glu(const float* __restrict__ hidden,
    const int* __restrict__ mask,const float* __restrict__ glu1w,
    const float* __restrict__ glu1b,const float* __restrict__ glu2w,
    const float* __restrict__ w2){
  extern __shared__ float sm[];
  float* g1t=sm;        // 16384 [e][d]
  float* hS =sm+16384;  // 6400
  float* nhS=sm+22784;  // 6400
  float* hs =sm+29184;  // 128
  float* t2 =sm+29312;  // 128
  float* bet=sm+29440;  // 64
  float* w2s=sm+29504;  // 128
  float* b1s=sm+29632;  // 128
  int b=blockIdx.x,t=threadIdx.x,warp=t>>5,lane=t&31;
  for(int i=t;i<16384;i+=256){ int e=i>>7,d=i&127; g1t[i]=glu1w[d*128+e]; }
  for(int i=t;i<6400;i+=256){ hS[i]=hidden[(size_t)b*6400+i]; nhS[i]=g_NH[(size_t)b*6400+i]; }
  if(t<128){ w2s[t]=w2[t]; b1s[t]=glu1b[t]; }
  __syncthreads();
  if(t<128){
    float a=0.f,ms=0.f;
    for(int l=0;l<50;l++){ float mv=(float)mask[b*50+l]; a+=hS[l*128+t]*mv; ms+=mv; }
    hs[t]=a/ms;
  }
  __syncthreads();
  if(t<128){
    float a=0.f;
    for(int e=0;e<128;e++) a+=hs[e]*glu2w[t*128+e];
    t2[t]=a;
  }
  __syncthreads();
  const float4* G14=(const float4*)g1t;
  for(int lb=0;lb<56;lb+=8){
    int l=lb+warp;
    if(l<50){
      const float4* N4=(const float4*)(nhS+l*128);
      float a0=0,a1=0,a2=0,a3=0;
      #pragma unroll 4
      for(int e4=0;e4<32;e4++){
        float4 a=N4[e4];
        float4 w=G14[(e4*4+0)*32+lane];
        a0+=a.x*w.x; a1+=a.x*w.y; a2+=a.x*w.z; a3+=a.x*w.w;
        w=G14[(e4*4+1)*32+lane];
        a0+=a.y*w.x; a1+=a.y*w.y; a2+=a.y*w.z; a3+=a.y*w.w;
        w=G14[(e4*4+2)*32+lane];
        a0+=a.z*w.x; a1+=a.z*w.y; a2+=a.z*w.z; a3+=a.z*w.w;
        w=G14[(e4*4+3)*32+lane];
        a0+=a.w*w.x; a1+=a.w*w.y; a2+=a.w*w.z; a3+=a.w*w.w;
      }
      int d0=lane*4;
      a0=1.f/(1.f+expf(-(a0+b1s[d0]+t2[d0])));
      a1=1.f/(1.f+expf(-(a1+b1s[d0+1]+t2[d0+1])));
      a2=1.f/(1.f+expf(-(a2+b1s[d0+2]+t2[d0+2])));
      a3=1.f/(1.f+expf(-(a3+b1s[d0+3]+t2[d0+3])));
      float p=a0*w2s[d0]+a1*w2s[d0+1]+a2*w2s[d0+2]+a3*w2s[d0+3];
      for(int o=16;o;o>>=1) p+=__shfl_xor_sync(0xffffffffu,p,o);
      if(lane==0) bet[l]=p*(float)mask[b*50+l];
    }
  }
  __syncthreads();
  if(t<128){
    float a=0.f;
    for(int l=0;l<50;l++) a+=bet[l]*hS[l*128+t];
    g_SEL[b*128+t]=a;
  }
}

// ---------------- neighbor top-k ----------------
__global__ void __launch_bounds__(128) k_nbr(){
  extern __shared__ float sm[];
  float* sel=sm;  // 16384
  __shared__ float nrm[128];
  __shared__ float ev[128];
  __shared__ float tv[9];
  __shared__ int   ti[9];
  __shared__ float red[4];
  int b=blockIdx.x,t=threadIdx.x;
  for(int i=t;i<16384;i+=128) sel[i]=g_SEL[i];
  __syncthreads();
  { float a=0.f;
    for(int d=0;d<128;d++){ float v=sel[t*128+d]; a+=v*v; }
    nrm[t]=sqrtf(a+128e-6f); }
  __syncthreads();
  float dot=0.f;
  for(int d=0;d<128;d++) dot+=sel[b*128+d]*sel[t*128+d];
  float e=dot/(nrm[b]*nrm[t]);
  float mx=e;
  for(int o=16;o;o>>=1) mx=fmaxf(mx,__shfl_xor_sync(0xffffffffu,mx,o));
  if((t&31)==0) red[t>>5]=mx;
  __syncthreads();
  mx=fmaxf(fmaxf(red[0],red[1]),fmaxf(red[2],red[3]));
  float ex=expf(e-mx);
  float ss=ex;
  for(int o=16;o;o>>=1) ss+=__shfl_xor_sync(0xffffffffu,ss,o);
  __syncthreads();
  if((t&31)==0) red[t>>5]=ss;
  __syncthreads();
  ss=red[0]+red[1]+red[2]+red[3];
  ev[t]=ex/ss;
  __syncthreads();
  if(t==0){
    for(int k=0;k<9;k++){
      float bv=-1.f; int bi=0;
      for(int j=0;j<128;j++) if(ev[j]>bv){ bv=ev[j]; bi=j; }
      tv[k]=bv; ti[k]=bi; ev[bi]=-2.f;
    }
    float m2=tv[0],s2=0.f;
    for(int k=0;k<9;k++){ tv[k]=expf(tv[k]-m2); s2+=tv[k]; }
    float inv=1.f/s2;
    for(int k=0;k<9;k++) tv[k]*=inv;
  }
  __syncthreads();
  float nb=0.f;
  #pragma unroll
  for(int k=0;k<9;k++) nb+=tv[k]*sel[ti[k]*128+t];
  g_SEL2T[t*128+b]=sel[b*128+t]+nb;
}

// ---------------- scores GEMM (FFMA2) ----------------
__global__ void __launch_bounds__(256) k_scores(const float* __restrict__ emb,
                                                float* __restrict__ outp){
  extern __shared__ float sm[];
  float* selT=sm;        // 16384 [e][b]
  float* embT=sm+16384;  // 128*129 [e][j] stride 129
  int t=threadIdx.x;
  int j0=blockIdx.x*128;
  for(int i=t;i<16384;i+=256) selT[i]=g_SEL2T[i];
  for(int i=t;i<16384;i+=256){
    int j=i>>7,e=i&127;
    int node=1+j0+j;
    embT[e*129+j]=(node<100000)?emb[(size_t)node*128+e]:0.f;
  }
  __syncthreads();
  int j=t&127,bh=t>>7;
  unsigned long long acc2[32];
  #pragma unroll
  for(int q=0;q<32;q++) acc2[q]=0ull;
  const ulonglong2* S8=(const ulonglong2*)selT;
  #pragma unroll 2
  for(int e=0;e<128;e++){
    float evv=embT[e*129+j];
    unsigned long long ev2=f2pack(evv,evv);
    const ulonglong2* s=&S8[e*32+bh*16];
    #pragma unroll
    for(int q=0;q<16;q++){
      ulonglong2 u=s[q];
      ffma2(acc2[q*2+0],ev2,u.x);
      ffma2(acc2[q*2+1],ev2,u.y);
    }
  }
  if(j0+j<99999){
    #pragma unroll
    for(int q=0;q<32;q++){
      float lo,hi;
      f2unpack(acc2[q],lo,hi);
      int b=bh*64+q*2;
      outp[(size_t)b*99999+j0+j]=lo;
      outp[(size_t)(b+1)*99999+j0+j]=hi;
    }
  }
}

// ---------------- launch ----------------
extern "C" void kernel_launch(void* const* d_in,const int* in_sizes,int n_in,
                              void* d_out,int out_size){
  const int*   inputs =(const int*)d_in[0];
  const int*   adj    =(const int*)d_in[1];
  const int*   mask   =(const int*)d_in[2];
  const int*   item   =(const int*)d_in[3];
  const int*   adj_all=(const int*)d_in[5];
  const float* num_w  =(const float*)d_in[6];
  const float* emb    =(const float*)d_in[7];
  const float* pos    =(const float*)d_in[8];
  const float* a_local=(const float*)d_in[9];
  const float* gw1    =(const float*)d_in[10];
  const float* gw2    =(const float*)d_in[11];
  const float* gw3    =(const float*)d_in[12];
  const float* w1     =(const float*)d_in[13];
  const float* w2     =(const float*)d_in[14];
  const float* g1w    =(const float*)d_in[15];
  const float* g1b    =(const float*)d_in[16];
  const float* g2w    =(const float*)d_in[17];
  float* out=(float*)d_out;

  const size_t SM_ATT=24896u*4u;   // 99,584 B -> 2 blocks/SM
  const size_t SM_LIN=40960u*4u;   // 163,840 B -> 1 block/SM
  const size_t SM_GLU=29760u*4u;
  const size_t SM_SC =32896u*4u;
  const size_t SM_NBR=16384u*4u;
  cudaFuncSetAttribute(k_att2,  cudaFuncAttributeMaxDynamicSharedMemorySize,(int)SM_ATT);
  cudaFuncSetAttribute(k_attm2, cudaFuncAttributeMaxDynamicSharedMemorySize,(int)SM_ATT);
  cudaFuncSetAttribute(k_lin,   cudaFuncAttributeMaxDynamicSharedMemorySize,(int)SM_LIN);
  cudaFuncSetAttribute(k_glu,   cudaFuncAttributeMaxDynamicSharedMemorySize,(int)SM_GLU);
  cudaFuncSetAttribute(k_scores,cudaFuncAttributeMaxDynamicSharedMemorySize,(int)SM_SC);
  cudaFuncSetAttribute(k_nbr,   cudaFuncAttributeMaxDynamicSharedMemorySize,(int)SM_NBR);

  k_prep1<<<200,256>>>(inputs,adj_all,num_w);
  k_prep2<<<1600,256>>>(adj_all,num_w);
  k_sess<<<128,128>>>(item,mask,emb);
  // hop 0: flattened mode0+mode1 attention (7296 chunks over 296 resident blocks)
  k_att2<<<296,256,SM_ATT>>>(25,emb,gw1,gw2);                        // -> g_NG0, g_NG1
  k_perm<<<1,128>>>();
  k_local<<<128,256>>>(inputs,adj,emb,a_local);
  k_lin<<<148,256,SM_LIN>>>(6400,0,inputs,emb,0,gw3,0);              // -> g_A0
  k_lin<<<148,256,SM_LIN>>>(51200,1,0,emb,0,gw3,0);                  // -> g_A1
  // hop 1 (896 chunks over 224 blocks = 1 wave)
  k_attm2<<<224,256,SM_ATT>>>(4,gw1+129*128,gw2+128);                // -> g_NG0
  k_lin<<<148,256,SM_LIN>>>(6400,2,0,0,0,gw3+256*128,out);           // -> g_HG + out (fused mix)
  // outputs
  k_ssl<<<128,128>>>();
  k_fin<<<1,128>>>(out);
  // scores head
  k_lin<<<148,256,SM_LIN>>>(6400,3,0,pos,out,w1,0);                  // -> g_NH
  k_glu<<<128,256,SM_GLU>>>(out,mask,g1w,g1b,g2w,w2);
  k_nbr<<<128,128,SM_NBR>>>();
  k_scores<<<782,256,SM_SC>>>(emb,out+819201);
}

// round 15
// speedup vs baseline: 1.1077x; 1.1077x over previous
#include <cuda_runtime.h>
#include <math.h>

// ---------------- f32x2 packed-FMA helpers (bitwise = 2x IEEE fp32 FMA) ----
__device__ __forceinline__ unsigned long long f2pack(float x,float y){
  unsigned long long r;
  asm("mov.b64 %0,{%1,%2};":"=l"(r):"r"(__float_as_uint(x)),"r"(__float_as_uint(y)));
  return r;
}
__device__ __forceinline__ void f2unpack(unsigned long long v,float&x,float&y){
  unsigned ux,uy;
  asm("mov.b64 {%0,%1},%2;":"=r"(ux),"=r"(uy):"l"(v));
  x=__uint_as_float(ux); y=__uint_as_float(uy);
}
__device__ __forceinline__ void ffma2(unsigned long long&d,unsigned long long a,unsigned long long b){
  asm("fma.rn.f32x2 %0,%1,%2,%0;":"+l"(d):"l"(a),"l"(b));
}

// ---------------- scratch ----------------
__device__ float g_SESS[128*128];
__device__ int   g_IN1[128*400];
__device__ float g_W0 [128*400];
__device__ int   g_IN2[128*3200];
__device__ float g_W1n[128*3200];
__device__ float g_NG0[128*50*128];
__device__ float g_NG1[128*400*128];
__device__ float g_A0 [128*50*128];
__device__ float g_A1 [128*400*128];
__device__ float g_HL [128*50*128];
__device__ float g_HG [128*50*128];
__device__ float g_NH [128*50*128];
__device__ float g_SEL[128*128];
__device__ float g_SEL2T[128*128];
__device__ float g_LP[128];
__device__ int   g_PR[128];
__device__ int   g_PC[64];

// ---------------- threefry ----------------
__device__ __forceinline__ void tf(unsigned k0,unsigned k1,unsigned x0,unsigned x1,
                                   unsigned&o0,unsigned&o1){
  unsigned ks2=k0^k1^0x1BD11BDAu;
  x0+=k0; x1+=k1;
#define RND(r) {x0+=x1; x1=(x1<<(r))|(x1>>(32-(r))); x1^=x0;}
  RND(13)RND(15)RND(26)RND(6)   x0+=k1;  x1+=ks2+1u;
  RND(17)RND(29)RND(16)RND(24)  x0+=ks2; x1+=k0+2u;
  RND(13)RND(15)RND(26)RND(6)   x0+=k0;  x1+=k1+3u;
  RND(17)RND(29)RND(16)RND(24)  x0+=k1;  x1+=ks2+4u;
  RND(13)RND(15)RND(26)RND(6)   x0+=ks2; x1+=k0+5u;
#undef RND
  o0=x0; o1=x1;
}

__global__ void k_perm(){
  __shared__ unsigned keys[4];
  __shared__ unsigned br[128];
  __shared__ unsigned bc[64];
  int t=threadIdx.x;
  if(t==0){
    unsigned u0,u1,v0,v1,p0,p1,q0,q1;
    tf(0u,42u,0u,2u,u0,u1); tf(0u,42u,1u,3u,v0,v1);
    unsigned kr0=u0,kr1=v0,kc0=u1,kc1=v1;
    tf(kr0,kr1,0u,2u,p0,p1); tf(kr0,kr1,1u,3u,q0,q1);
    keys[0]=p1; keys[1]=q1;
    tf(kc0,kc1,0u,2u,p0,p1); tf(kc0,kc1,1u,3u,q0,q1);
    keys[2]=p1; keys[3]=q1;
  }
  __syncthreads();
  { int j=t&63; unsigned w0,w1;
    tf(keys[0],keys[1],(unsigned)j,(unsigned)(j+64),w0,w1);
    br[t]=(t<64)?w0:w1; }
  if(t<50){ int j=(t<25)?t:t-25; unsigned w0,w1;
    tf(keys[2],keys[3],(unsigned)j,(unsigned)(j+25),w0,w1);
    bc[t]=(t<25)?w0:w1; }
  __syncthreads();
  { unsigned mine=br[t]; int r=0;
    for(int j=0;j<128;j++){ unsigned bj=br[j]; r+=(bj<mine)||(bj==mine&&j<t); }
    g_PR[r]=t; }
  if(t<50){ unsigned mine=bc[t]; int r=0;
    for(int j=0;j<50;j++){ unsigned bj=bc[j]; r+=(bj<mine)||(bj==mine&&j<t); }
    g_PC[r]=t; }
}

// ---------------- prep ----------------
__global__ void k_prep1(const int* __restrict__ inputs,const int* __restrict__ adj_all,
                        const float* __restrict__ num_w){
  int t=blockIdx.x*blockDim.x+threadIdx.x;
  if(t<128*400){
    int b=t/400,m=t%400;
    int node=inputs[b*50+(m>>3)];
    g_IN1[t]=adj_all[node*8+(m&7)];
    g_W0[t]=num_w[node*8+(m&7)];
  }
}
__global__ void k_prep2(const int* __restrict__ adj_all,const float* __restrict__ num_w){
  int t=blockIdx.x*blockDim.x+threadIdx.x;
  if(t<128*3200){
    int b=t/3200,m=t%3200;
    int node=g_IN1[b*400+(m>>3)];
    g_IN2[t]=adj_all[node*8+(m&7)];
    g_W1n[t]=num_w[node*8+(m&7)];
  }
}
__global__ void k_sess(const int* __restrict__ item,const int* __restrict__ mask,
                       const float* __restrict__ emb){
  int b=blockIdx.x,d=threadIdx.x;
  float acc=0.f,ms=0.f;
  for(int l=0;l<50;l++){
    float mv=(float)mask[b*50+l];
    acc+=emb[(size_t)item[b*50+l]*128+d]*mv; ms+=mv;
  }
  g_SESS[b*128+d]=acc/ms;
}

// ---------------- local agg (split ii range across blockIdx.y) -------------
__global__ void __launch_bounds__(256) k_local(const int* __restrict__ inputs,
    const int* __restrict__ adj,const float* __restrict__ emb,
    const float* __restrict__ a_local){
  __shared__ float hs[6400];
  __shared__ float al[512];
  __shared__ float hik[512];
  __shared__ float es[50];
  __shared__ float att[50];
  int b=blockIdx.x,t=threadIdx.x,warp=t>>5,lane=t&31;
  int ii0=blockIdx.y*25, ii1=ii0+25;
  for(int i=t;i<6400;i+=256) hs[i]=emb[(size_t)inputs[b*50+(i>>7)]*128+(i&127)];
  for(int i=t;i<512;i+=256) al[i]=a_local[i];
  __syncthreads();
  for(int ii=ii0;ii<ii1;ii++){
    if(t<128){
      float hv=hs[ii*128+t];
      #pragma unroll
      for(int k=0;k<4;k++) hik[k*128+t]=hv*al[k*128+t];
    }
    __syncthreads();
    for(int jj=warp;jj<50;jj+=8){
      int aj=adj[b*2500+ii*50+jj];
      int k=aj>0?aj-1:0;
      const float4* hk=(const float4*)(hik+k*128);
      const float4* hj=(const float4*)(hs+jj*128);
      float4 p=hk[lane],q=hj[lane];
      float v=p.x*q.x+p.y*q.y+p.z*q.z+p.w*q.w;
      for(int o=16;o;o>>=1) v+=__shfl_xor_sync(0xffffffffu,v,o);
      float e=(aj>0)?(v>0.f?v:0.2f*v):-9e15f;
      if(lane==0) es[jj]=e;
    }
    __syncthreads();
    if(warp==0){
      float m1=-3.4e38f;
      for(int j=lane;j<50;j+=32) m1=fmaxf(m1,es[j]);
      for(int o=16;o;o>>=1) m1=fmaxf(m1,__shfl_xor_sync(0xffffffffu,m1,o));
      float ss=0.f;
      for(int j=lane;j<50;j+=32){ float ex=expf(es[j]-m1); att[j]=ex; ss+=ex; }
      for(int o=16;o;o>>=1) ss+=__shfl_xor_sync(0xffffffffu,ss,o);
      float inv=1.f/ss;
      for(int j=lane;j<50;j+=32) att[j]*=inv;
    }
    __syncthreads();
    if(t<128){
      float acc=0.f;
      for(int j=0;j<50;j++) acc+=att[j]*hs[j*128+t];
      g_HL[(size_t)b*6400+ii*128+t]=acc;
    }
    __syncthreads();
  }
}

// ===== attention core: warp w <-> row m0+w, all 8 samples warp-local =======
#define ATT_COMPUTE(OUTNG,MTOT)                                                \
  {                                                                            \
    __syncwarp();                                                              \
    unsigned long long acc2[8][2];                                             \
    _Pragma("unroll")                                                          \
    for(int ss=0;ss<8;ss++){ acc2[ss][0]=0ull; acc2[ss][1]=0ull; }             \
    for(int e4=0;e4<32;e4++){                                                  \
      ulonglong2 w0 =WT8[(e4*4+0)*32+lane];                                    \
      ulonglong2 w1v=WT8[(e4*4+1)*32+lane];                                    \
      ulonglong2 w2v=WT8[(e4*4+2)*32+lane];                                    \
      ulonglong2 w3v=WT8[(e4*4+3)*32+lane];                                    \
      _Pragma("unroll")                                                        \
      for(int ss=0;ss<8;ss++){                                                 \
        float4 a=NV4[(w*8+ss)*32+e4];                                          \
        unsigned long long ax=f2pack(a.x,a.x);                                 \
        unsigned long long ay=f2pack(a.y,a.y);                                 \
        unsigned long long az=f2pack(a.z,a.z);                                 \
        unsigned long long aw=f2pack(a.w,a.w);                                 \
        ffma2(acc2[ss][0],ax,w0.x);  ffma2(acc2[ss][1],ax,w0.y);               \
        ffma2(acc2[ss][0],ay,w1v.x); ffma2(acc2[ss][1],ay,w1v.y);              \
        ffma2(acc2[ss][0],az,w2v.x); ffma2(acc2[ss][1],az,w2v.y);              \
        ffma2(acc2[ss][0],aw,w3v.x); ffma2(acc2[ss][1],aw,w3v.y);              \
      }                                                                        \
    }                                                                          \
    int d0=lane*4;                                                             \
    float pr[8];                                                               \
    _Pragma("unroll")                                                          \
    for(int ss=0;ss<8;ss++){                                                   \
      float a0,a1,a2,a3;                                                       \
      f2unpack(acc2[ss][0],a0,a1);                                             \
      f2unpack(acc2[ss][1],a2,a3);                                             \
      float nwv=nws[w*8+ss];                                                   \
      float v0=a0+nwv*w129[d0];                                                \
      float v1=a1+nwv*w129[d0+1];                                              \
      float v2=a2+nwv*w129[d0+2];                                              \
      float v3=a3+nwv*w129[d0+3];                                              \
      v0=v0>0.f?v0:0.2f*v0; v1=v1>0.f?v1:0.2f*v1;                              \
      v2=v2>0.f?v2:0.2f*v2; v3=v3>0.f?v3:0.2f*v3;                              \
      float p=v0*g2[d0]+v1*g2[d0+1]+v2*g2[d0+2]+v3*g2[d0+3];                   \
      for(int o=16;o;o>>=1) p+=__shfl_xor_sync(0xffffffffu,p,o);               \
      pr[ss]=p;                                                                \
    }                                                                          \
    float mx=pr[0];                                                            \
    _Pragma("unroll")                                                          \
    for(int i=1;i<8;i++) mx=fmaxf(mx,pr[i]);                                   \
    float exr[8];                                                              \
    _Pragma("unroll")                                                          \
    for(int i=0;i<8;i++) exr[i]=expf(pr[i]-mx);                                \
    float ssum=0.f;                                                            \
    _Pragma("unroll")                                                          \
    for(int i=0;i<8;i++) ssum+=exr[i];                                         \
    float inv=1.f/ssum;                                                        \
    if(m0+w<MTOT){                                                             \
      float o0=0.f,o1=0.f,o2=0.f,o3=0.f;                                       \
      _Pragma("unroll")                                                        \
      for(int i=0;i<8;i++){                                                    \
        float ali=exr[i]*inv;                                                  \
        float4 r=NV4[(w*8+i)*32+lane];                                         \
        o0+=ali*r.x; o1+=ali*r.y; o2+=ali*r.z; o3+=ali*r.w;                    \
      }                                                                        \
      float4 ov; ov.x=o0; ov.y=o1; ov.z=o2; ov.w=o3;                           \
      ((float4*)OUTNG)[((size_t)b*MTOT+(m0+w))*32+lane]=ov;                    \
    }                                                                          \
  }

// ---------------- hop-0 global attention: flattened queue ------------------
__global__ void __launch_bounds__(256) k_att2(int Q,
    const float* __restrict__ emb,const float* __restrict__ gw1h,
    const float* __restrict__ gw2h){
  extern __shared__ float sm[];
  float* wt  = sm;         // 16384 [e][d]
  float* nv  = sm+16384;   // 8192 : 64 rows of 128
  float* w129= sm+24576;   // 128
  float* g2  = sm+24704;   // 128
  float* nws = sm+24832;   // 64
  int t=threadIdx.x,lane=t&31,w=t>>5;
  if(t<128){ w129[t]=gw1h[16384+t]; g2[t]=gw2h[t]; }
  __syncthreads();
  const ulonglong2* WT8=(const ulonglong2*)wt;
  const float4* NV4=(const float4*)nv;
  int g0=blockIdx.x*Q, g1=min(g0+Q,7296);
  int cur_b=-1;
  float4 pfv[8];
  float pfw=0.f;
#define ATT2_PRE(G) do{ \
    int bb=(G)/57, cc=(G)-bb*57; \
    int is1p=(cc>=7); \
    int Mt=is1p?400:50; \
    int mm0=(is1p?(cc-7):cc)*8; \
    const int* ni=is1p?g_IN2:g_IN1; \
    const float* nwq=is1p?g_W1n:g_W0; \
    int mp=min(mm0+w,Mt-1); \
    size_t bp=((size_t)bb*Mt+mp)*8; \
    _Pragma("unroll") \
    for(int ss=0;ss<8;ss++) \
      pfv[ss]=((const float4*)emb)[(size_t)ni[bp+ss]*32+lane]; \
    if(lane<8) pfw=nwq[bp+lane]; \
  }while(0)
  if(g0<g1) ATT2_PRE(g0);
  for(int g=g0;g<g1;g++){
    int b=g/57, c=g-b*57;
    if(b!=cur_b){
      __syncthreads();
      for(int i=t;i<16384;i+=256) wt[i]=g_SESS[b*128+(i>>7)]*gw1h[i];
      cur_b=b;
      __syncthreads();
    }
    int is1=(c>=7);
    int Mtot=is1?400:50;
    int m0=(is1?(c-7):c)*8;
    float* outNG = is1?g_NG1:g_NG0;
    #pragma unroll
    for(int ss=0;ss<8;ss++)
      ((float4*)nv)[(w*8+ss)*32+lane]=pfv[ss];
    if(lane<8) nws[w*8+lane]=pfw;
    if(g+1<g1) ATT2_PRE(g+1);
    ATT_COMPUTE(outNG,Mtot)
  }
#undef ATT2_PRE
}

// ---------------- hop-1 attention (src = g_A1 rows) -------------------------
__global__ void __launch_bounds__(256) k_attm2(int Q,
    const float* __restrict__ gw1h,const float* __restrict__ gw2h){
  extern __shared__ float sm[];
  float* wt  = sm;
  float* nv  = sm+16384;
  float* w129= sm+24576;
  float* g2  = sm+24704;
  float* nws = sm+24832;
  int t=threadIdx.x,lane=t&31,w=t>>5;
  if(t<128){ w129[t]=gw1h[16384+t]; g2[t]=gw2h[t]; }
  __syncthreads();
  const ulonglong2* WT8=(const ulonglong2*)wt;
  const float4* NV4=(const float4*)nv;
  int g0=blockIdx.x*Q, g1=min(g0+Q,896);
  int cur_b=-1;
  float4 pfv[8];
  float pfw=0.f;
#define ATTM_PRE(G) do{ \
    int bb=(G)/7, cc=(G)-bb*7; \
    int mp=min(cc*8+w,49); \
    size_t bp=((size_t)bb*50+mp)*8; \
    _Pragma("unroll") \
    for(int ss=0;ss<8;ss++) \
      pfv[ss]=((const float4*)g_A1)[(bp+ss)*32+lane]; \
    if(lane<8) pfw=g_W0[bp+lane]; \
  }while(0)
  if(g0<g1) ATTM_PRE(g0);
  for(int g=g0;g<g1;g++){
    int b=g/7, c=g-b*7;
    if(b!=cur_b){
      __syncthreads();
      for(int i=t;i<16384;i+=256) wt[i]=g_SESS[b*128+(i>>7)]*gw1h[i];
      cur_b=b;
      __syncthreads();
    }
    const int Mtot=50;
    int m0=c*8;
    #pragma unroll
    for(int ss=0;ss<8;ss++)
      ((float4*)nv)[(w*8+ss)*32+lane]=pfv[ss];
    if(lane<8) nws[w*8+lane]=pfw;
    if(g+1<g1) ATTM_PRE(g+1);
    ATT_COMPUTE(g_NG0,Mtot)
  }
#undef ATTM_PRE
}

// -------- linear (concat 256 -> 128), persistent, FFMA2, double-buffered ---
// cfg2 additionally writes outmix = g_HL + relu(v)  (fused k_mix)
__global__ void __launch_bounds__(256) k_lin(int nrows,int cfg,
    const int* __restrict__ idxtab,const float* __restrict__ extA,
    const float* __restrict__ extB,const float* __restrict__ w,
    float* __restrict__ outmix){
  extern __shared__ float sm[];
  float* ws=sm;          // 32768 [e][d]
  float* inT=sm+32768;   // 8192 [e][32]
  int t=threadIdx.x;
  for(int i=t;i<32768;i+=256) ws[i]=w[i];
  int ngroups=(nrows+31)>>5;
  float* outp=(cfg==0)?g_A0:(cfg==1)?g_A1:(cfg==2)?g_HG:g_NH;
  float pf[32];
  int grp=blockIdx.x;

#define LIN_LOAD_PF(GRP) do{ \
    int row0p=(GRP)*32; \
    _Pragma("unroll") \
    for(int k=0;k<32;k++){ \
      int i=t+k*256; int r=i&31,e=i>>5,row=row0p+r; \
      float v=0.f; \
      if(row<nrows){ \
        if(e<128){ \
          if(cfg==0)      v=extA[(size_t)idxtab[row]*128+e]; \
          else if(cfg==1) v=extA[(size_t)g_IN1[row]*128+e]; \
          else if(cfg==2) v=g_A0[(size_t)row*128+e]; \
          else            v=extA[(size_t)(row%50)*128+e]; \
        }else{ \
          int e2=e-128; \
          if(cfg==0)      v=g_NG0[(size_t)row*128+e2]; \
          else if(cfg==1) v=g_NG1[(size_t)row*128+e2]; \
          else if(cfg==2) v=g_NG0[(size_t)row*128+e2]; \
          else            v=extB[(size_t)row*128+e2]; \
        } \
      } \
      pf[k]=v; \
    } \
  }while(0)

  if(grp<ngroups) LIN_LOAD_PF(grp);
  for(;grp<ngroups;grp+=gridDim.x){
    __syncthreads();
    #pragma unroll
    for(int k=0;k<32;k++) inT[t+k*256]=pf[k];
    __syncthreads();
    int nxt=grp+gridDim.x;
    if(nxt<ngroups) LIN_LOAD_PF(nxt);
    int row0=grp*32;
    int d=t&127,rh=t>>7;
    unsigned long long acc2[8];
    #pragma unroll
    for(int q=0;q<8;q++) acc2[q]=0ull;
    const ulonglong2* I8=(const ulonglong2*)inT;
    #pragma unroll 8
    for(int e=0;e<256;e++){
      float wv=ws[e*128+d];
      unsigned long long wv2=f2pack(wv,wv);
      ulonglong2 u0=I8[e*8+rh*4+0];
      ulonglong2 u1=I8[e*8+rh*4+1];
      ulonglong2 u2=I8[e*8+rh*4+2];
      ulonglong2 u3=I8[e*8+rh*4+3];
      ffma2(acc2[0],wv2,u0.x); ffma2(acc2[1],wv2,u0.y);
      ffma2(acc2[2],wv2,u1.x); ffma2(acc2[3],wv2,u1.y);
      ffma2(acc2[4],wv2,u2.x); ffma2(acc2[5],wv2,u2.y);
      ffma2(acc2[6],wv2,u3.x); ffma2(acc2[7],wv2,u3.y);
    }
    #pragma unroll
    for(int q=0;q<8;q++){
      float lo,hi;
      f2unpack(acc2[q],lo,hi);
      int rlo=row0+rh*16+q*2;
      if(rlo<nrows){
        float v=(cfg==3)?tanhf(lo):fmaxf(lo,0.f);
        outp[(size_t)rlo*128+d]=v;
        if(cfg==2) outmix[(size_t)rlo*128+d]=g_HL[(size_t)rlo*128+d]+v;
      }
      if(rlo+1<nrows){
        float v=(cfg==3)?tanhf(hi):fmaxf(hi,0.f);
        outp[(size_t)(rlo+1)*128+d]=v;
        if(cfg==2) outmix[(size_t)(rlo+1)*128+d]=g_HL[(size_t)(rlo+1)*128+d]+v;
      }
    }
  }
#undef LIN_LOAD_PF
}

// ---------------- ssl ----------------
__global__ void k_ssl(){
  __shared__ float red[128];
  int b=blockIdx.x,t=threadIdx.x;
  int pb=g_PR[b];
  float pos=0.f,neg=0.f;
  for(int l=0;l<50;l++){
    float hl=g_HL[(size_t)b*6400+l*128+t];
    float hg=g_HG[(size_t)b*6400+l*128+t];
    pos+=hl*hg;
    neg+=hg*g_HL[(size_t)pb*6400+g_PC[l]*128+t];
  }
  float sp=1.f/(1.f+expf(-pos)),sn=1.f/(1.f+expf(-neg));
  float term=-logf(1e-8f+sp)-logf(1e-8f+1.f-sn);
  red[t]=term; __syncthreads();
  for(int o=64;o;o>>=1){ if(t<o) red[t]+=red[t+o]; __syncthreads(); }
  if(t==0) g_LP[b]=red[0];
}
__global__ void k_fin(float* __restrict__ out){
  __shared__ float r[128];
  int t=threadIdx.x;
  r[t]=g_LP[t]; __syncthreads();
  for(int o=64;o;o>>=1){ if(t<o) r[t]+=r[t+o]; __syncthreads(); }
  if(t==0) out[819200]=0.005f*r[0];
}

// ---------------- glu/select ----------------
__global__ void __launch_bounds__(256) k_glu(const float* __restrict__ hidden,
    const int* __restrict__ mask,const float* __restrict__ glu1w,
    const float* __restrict__ glu1b,const float* __restrict__ glu2w,
    const float* __restrict__ w2){
  extern __shared__ float sm[];
  float* g1t=sm;        // 16384 [e][d]
  float* hS =sm+16384;  // 6400
  float* nhS=sm+22784;  // 6400
  float* hs =sm+29184;  // 128
  float* t2 =sm+29312;  // 128
  float* bet=sm+29440;  // 64
  float* w2s=sm+29504;  // 128
  float* b1s=sm+29632;  // 128
  int b=blockIdx.x,t=threadIdx.x,warp=t>>5,lane=t&31;
  for(int i=t;i<16384;i+=256){ int e=i>>7,d=i&127; g1t[i]=glu1w[d*128+e]; }
  for(int i=t;i<6400;i+=256){ hS[i]=hidden[(size_t)b*6400+i]; nhS[i]=g_NH[(size_t)b*6400+i]; }
  if(t<128){ w2s[t]=w2[t]; b1s[t]=glu1b[t]; }
  __syncthreads();
  if(t<128){
    float a=0.f,ms=0.f;
    for(int l=0;l<50;l++){ float mv=(float)mask[b*50+l]; a+=hS[l*128+t]*mv; ms+=mv; }
    hs[t]=a/ms;
  }
  __syncthreads();
  if(t<128){
    float a=0.f;
    for(int e=0;e<128;e++) a+=hs[e]*glu2w[t*128+e];
    t2[t]=a;
  }
  __syncthreads();
  const float4* G14=(const float4*)g1t;
  for(int lb=0;lb<56;lb+=8){
    int l=lb+warp;
    if(l<50){
      const float4* N4=(const float4*)(nhS+l*128);
      float a0=0,a1=0,a2=0,a3=0;
      #pragma unroll 4
      for(int e4=0;e4<32;e4++){
        float4 a=N4[e4];
        float4 w=G14[(e4*4+0)*32+lane];
        a0+=a.x*w.x; a1+=a.x*w.y; a2+=a.x*w.z; a3+=a.x*w.w;
        w=G14[(e4*4+1)*32+lane];
        a0+=a.y*w.x; a1+=a.y*w.y; a2+=a.y*w.z; a3+=a.y*w.w;
        w=G14[(e4*4+2)*32+lane];
        a0+=a.z*w.x; a1+=a.z*w.y; a2+=a.z*w.z; a3+=a.z*w.w;
        w=G14[(e4*4+3)*32+lane];
        a0+=a.w*w.x; a1+=a.w*w.y; a2+=a.w*w.z; a3+=a.w*w.w;
      }
      int d0=lane*4;
      a0=1.f/(1.f+expf(-(a0+b1s[d0]+t2[d0])));
      a1=1.f/(1.f+expf(-(a1+b1s[d0+1]+t2[d0+1])));
      a2=1.f/(1.f+expf(-(a2+b1s[d0+2]+t2[d0+2])));
      a3=1.f/(1.f+expf(-(a3+b1s[d0+3]+t2[d0+3])));
      float p=a0*w2s[d0]+a1*w2s[d0+1]+a2*w2s[d0+2]+a3*w2s[d0+3];
      for(int o=16;o;o>>=1) p+=__shfl_xor_sync(0xffffffffu,p,o);
      if(lane==0) bet[l]=p*(float)mask[b*50+l];
    }
  }
  __syncthreads();
  if(t<128){
    float a=0.f;
    for(int l=0;l<50;l++) a+=bet[l]*hS[l*128+t];
    g_SEL[b*128+t]=a;
  }
}

// ---------------- neighbor top-k ----------------
__global__ void __launch_bounds__(128) k_nbr(){
  extern __shared__ float sm[];
  float* sel=sm;  // 16384
  __shared__ float nrm[128];
  __shared__ float ev[128];
  __shared__ float tv[9];
  __shared__ int   ti[9];
  __shared__ float red[4];
  int b=blockIdx.x,t=threadIdx.x;
  for(int i=t;i<16384;i+=128) sel[i]=g_SEL[i];
  __syncthreads();
  { float a=0.f;
    for(int d=0;d<128;d++){ float v=sel[t*128+d]; a+=v*v; }
    nrm[t]=sqrtf(a+128e-6f); }
  __syncthreads();
  float dot=0.f;
  for(int d=0;d<128;d++) dot+=sel[b*128+d]*sel[t*128+d];
  float e=dot/(nrm[b]*nrm[t]);
  float mx=e;
  for(int o=16;o;o>>=1) mx=fmaxf(mx,__shfl_xor_sync(0xffffffffu,mx,o));
  if((t&31)==0) red[t>>5]=mx;
  __syncthreads();
  mx=fmaxf(fmaxf(red[0],red[1]),fmaxf(red[2],red[3]));
  float ex=expf(e-mx);
  float ss=ex;
  for(int o=16;o;o>>=1) ss+=__shfl_xor_sync(0xffffffffu,ss,o);
  __syncthreads();
  if((t&31)==0) red[t>>5]=ss;
  __syncthreads();
  ss=red[0]+red[1]+red[2]+red[3];
  ev[t]=ex/ss;
  __syncthreads();
  if(t==0){
    for(int k=0;k<9;k++){
      float bv=-1.f; int bi=0;
      for(int j=0;j<128;j++) if(ev[j]>bv){ bv=ev[j]; bi=j; }
      tv[k]=bv; ti[k]=bi; ev[bi]=-2.f;
    }
    float m2=tv[0],s2=0.f;
    for(int k=0;k<9;k++){ tv[k]=expf(tv[k]-m2); s2+=tv[k]; }
    float inv=1.f/s2;
    for(int k=0;k<9;k++) tv[k]*=inv;
  }
  __syncthreads();
  float nb=0.f;
  #pragma unroll
  for(int k=0;k<9;k++) nb+=tv[k]*sel[ti[k]*128+t];
  g_SEL2T[t*128+b]=sel[b*128+t]+nb;
}

// ---------------- scores GEMM (FFMA2, 64-j tiles, 2 blocks/SM) --------------
__global__ void __launch_bounds__(256) k_scores(const float* __restrict__ emb,
                                                float* __restrict__ outp){
  extern __shared__ float sm[];
  float* selT=sm;        // 16384 [e][b]
  float* embT=sm+16384;  // 128*65 [e][j] stride 65 (64 j per tile)
  int t=threadIdx.x;
  int j0=blockIdx.x*64;
  for(int i=t;i<16384;i+=256) selT[i]=g_SEL2T[i];
  for(int i=t;i<8320;i+=256){
    int j=i/65,e=i%65;
    // layout [e][j]: index e*65+j ; fill by linear i over 128*65
  }
  for(int i=t;i<8192;i+=256){
    int j=i&63,e=i>>6;
    int node=1+j0+j;
    embT[e*65+j]=(node<100000)?emb[(size_t)node*128+e]:0.f;
  }
  __syncthreads();
  int j=t&63,bh=(t>>6)&3;   // bh in 0..3, b range bh*32..bh*32+31
  unsigned long long acc2[16];
  #pragma unroll
  for(int q=0;q<16;q++) acc2[q]=0ull;
  const ulonglong2* S8=(const ulonglong2*)selT;
  #pragma unroll 2
  for(int e=0;e<128;e++){
    float evv=embT[e*65+j];
    unsigned long long ev2=f2pack(evv,evv);
    const ulonglong2* s=&S8[e*32+bh*8];
    #pragma unroll
    for(int q=0;q<8;q++){
      ulonglong2 u=s[q];
      ffma2(acc2[q*2+0],ev2,u.x);
      ffma2(acc2[q*2+1],ev2,u.y);
    }
  }
  if(j0+j<99999){
    #pragma unroll
    for(int q=0;q<16;q++){
      float lo,hi;
      f2unpack(acc2[q],lo,hi);
      int b=bh*32+q*2;
      outp[(size_t)b*99999+j0+j]=lo;
      outp[(size_t)(b+1)*99999+j0+j]=hi;
    }
  }
}

// ---------------- launch ----------------
extern "C" void kernel_launch(void* const* d_in,const int* in_sizes,int n_in,
                              void* d_out,int out_size){
  const int*   inputs =(const int*)d_in[0];
  const int*   adj    =(const int*)d_in[1];
  const int*   mask   =(const int*)d_in[2];
  const int*   item   =(const int*)d_in[3];
  const int*   adj_all=(const int*)d_in[5];
  const float* num_w  =(const float*)d_in[6];
  const float* emb    =(const float*)d_in[7];
  const float* pos    =(const float*)d_in[8];
  const float* a_local=(const float*)d_in[9];
  const float* gw1    =(const float*)d_in[10];
  const float* gw2    =(const float*)d_in[11];
  const float* gw3    =(const float*)d_in[12];
  const float* w1     =(const float*)d_in[13];
  const float* w2     =(const float*)d_in[14];
  const float* g1w    =(const float*)d_in[15];
  const float* g1b    =(const float*)d_in[16];
  const float* g2w    =(const float*)d_in[17];
  float* out=(float*)d_out;

  const size_t SM_ATT=24896u*4u;   // 99,584 B -> 2 blocks/SM
  const size_t SM_LIN=40960u*4u;   // 163,840 B -> 1 block/SM
  const size_t SM_GLU=29760u*4u;
  const size_t SM_SC =24704u*4u;   // 98,816 B -> 2 blocks/SM
  const size_t SM_NBR=16384u*4u;
  cudaFuncSetAttribute(k_att2,  cudaFuncAttributeMaxDynamicSharedMemorySize,(int)SM_ATT);
  cudaFuncSetAttribute(k_attm2, cudaFuncAttributeMaxDynamicSharedMemorySize,(int)SM_ATT);
  cudaFuncSetAttribute(k_lin,   cudaFuncAttributeMaxDynamicSharedMemorySize,(int)SM_LIN);
  cudaFuncSetAttribute(k_glu,   cudaFuncAttributeMaxDynamicSharedMemorySize,(int)SM_GLU);
  cudaFuncSetAttribute(k_scores,cudaFuncAttributeMaxDynamicSharedMemorySize,(int)SM_SC);
  cudaFuncSetAttribute(k_nbr,   cudaFuncAttributeMaxDynamicSharedMemorySize,(int)SM_NBR);

  k_prep1<<<200,256>>>(inputs,adj_all,num_w);
  k_prep2<<<1600,256>>>(adj_all,num_w);
  k_sess<<<128,128>>>(item,mask,emb);
  // hop 0: flattened mode0+mode1 attention (7296 chunks over 296 resident blocks)
  k_att2<<<296,256,SM_ATT>>>(25,emb,gw1,gw2);                        // -> g_NG0, g_NG1
  k_perm<<<1,128>>>();
  k_local<<<dim3(128,2),256>>>(inputs,adj,emb,a_local);
  k_lin<<<148,256,SM_LIN>>>(6400,0,inputs,emb,0,gw3,0);              // -> g_A0
  k_lin<<<148,256,SM_LIN>>>(51200,1,0,emb,0,gw3,0);                  // -> g_A1
  // hop 1 (896 chunks over 224 blocks = 1 wave)
  k_attm2<<<224,256,SM_ATT>>>(4,gw1+129*128,gw2+128);                // -> g_NG0
  k_lin<<<148,256,SM_LIN>>>(6400,2,0,0,0,gw3+256*128,out);           // -> g_HG + out (fused mix)
  // outputs
  k_ssl<<<128,128>>>();
  k_fin<<<1,128>>>(out);
  // scores head
  k_lin<<<148,256,SM_LIN>>>(6400,3,0,pos,out,w1,0);                  // -> g_NH
  k_glu<<<128,256,SM_GLU>>>(out,mask,g1w,g1b,g2w,w2);
  k_nbr<<<128,128,SM_NBR>>>();
  k_scores<<<1563,256,SM_SC>>>(emb,out+819201);
}

// round 16
// speedup vs baseline: 1.1650x; 1.0517x over previous
#include <cuda_runtime.h>
#include <math.h>

// ---------------- f32x2 packed-FMA helpers (bitwise = 2x IEEE fp32 FMA) ----
__device__ __forceinline__ unsigned long long f2pack(float x,float y){
  unsigned long long r;
  asm("mov.b64 %0,{%1,%2};":"=l"(r):"r"(__float_as_uint(x)),"r"(__float_as_uint(y)));
  return r;
}
__device__ __forceinline__ void f2unpack(unsigned long long v,float&x,float&y){
  unsigned ux,uy;
  asm("mov.b64 {%0,%1},%2;":"=r"(ux),"=r"(uy):"l"(v));
  x=__uint_as_float(ux); y=__uint_as_float(uy);
}
__device__ __forceinline__ void ffma2(unsigned long long&d,unsigned long long a,unsigned long long b){
  asm("fma.rn.f32x2 %0,%1,%2,%0;":"+l"(d):"l"(a),"l"(b));
}

// ---------------- scratch ----------------
__device__ float g_SESS[128*128];
__device__ int   g_IN1[128*400];
__device__ float g_W0 [128*400];
__device__ int   g_IN2[128*3200];
__device__ float g_W1n[128*3200];
__device__ float g_NG0[128*50*128];
__device__ float g_NG1[128*400*128];
__device__ float g_A0 [128*50*128];
__device__ float g_A1 [128*400*128];
__device__ float g_HL [128*50*128];
__device__ float g_HG [128*50*128];
__device__ float g_NH [128*50*128];
__device__ float g_SEL[128*128];
__device__ float g_SEL2T[128*128];
__device__ float g_LP[128];
__device__ int   g_PR[128];
__device__ int   g_PC[64];

// ---------------- threefry ----------------
__device__ __forceinline__ void tf(unsigned k0,unsigned k1,unsigned x0,unsigned x1,
                                   unsigned&o0,unsigned&o1){
  unsigned ks2=k0^k1^0x1BD11BDAu;
  x0+=k0; x1+=k1;
#define RND(r) {x0+=x1; x1=(x1<<(r))|(x1>>(32-(r))); x1^=x0;}
  RND(13)RND(15)RND(26)RND(6)   x0+=k1;  x1+=ks2+1u;
  RND(17)RND(29)RND(16)RND(24)  x0+=ks2; x1+=k0+2u;
  RND(13)RND(15)RND(26)RND(6)   x0+=k0;  x1+=k1+3u;
  RND(17)RND(29)RND(16)RND(24)  x0+=k1;  x1+=ks2+4u;
  RND(13)RND(15)RND(26)RND(6)   x0+=ks2; x1+=k0+5u;
#undef RND
  o0=x0; o1=x1;
}

__global__ void k_perm(){
  __shared__ unsigned keys[4];
  __shared__ unsigned br[128];
  __shared__ unsigned bc[64];
  int t=threadIdx.x;
  if(t==0){
    unsigned u0,u1,v0,v1,p0,p1,q0,q1;
    tf(0u,42u,0u,2u,u0,u1); tf(0u,42u,1u,3u,v0,v1);
    unsigned kr0=u0,kr1=v0,kc0=u1,kc1=v1;
    tf(kr0,kr1,0u,2u,p0,p1); tf(kr0,kr1,1u,3u,q0,q1);
    keys[0]=p1; keys[1]=q1;
    tf(kc0,kc1,0u,2u,p0,p1); tf(kc0,kc1,1u,3u,q0,q1);
    keys[2]=p1; keys[3]=q1;
  }
  __syncthreads();
  { int j=t&63; unsigned w0,w1;
    tf(keys[0],keys[1],(unsigned)j,(unsigned)(j+64),w0,w1);
    br[t]=(t<64)?w0:w1; }
  if(t<50){ int j=(t<25)?t:t-25; unsigned w0,w1;
    tf(keys[2],keys[3],(unsigned)j,(unsigned)(j+25),w0,w1);
    bc[t]=(t<25)?w0:w1; }
  __syncthreads();
  { unsigned mine=br[t]; int r=0;
    for(int j=0;j<128;j++){ unsigned bj=br[j]; r+=(bj<mine)||(bj==mine&&j<t); }
    g_PR[r]=t; }
  if(t<50){ unsigned mine=bc[t]; int r=0;
    for(int j=0;j<50;j++){ unsigned bj=bc[j]; r+=(bj<mine)||(bj==mine&&j<t); }
    g_PC[r]=t; }
}

// ---------------- prep ----------------
__global__ void k_prep1(const int* __restrict__ inputs,const int* __restrict__ adj_all,
                        const float* __restrict__ num_w){
  int t=blockIdx.x*blockDim.x+threadIdx.x;
  if(t<128*400){
    int b=t/400,m=t%400;
    int node=inputs[b*50+(m>>3)];
    g_IN1[t]=adj_all[node*8+(m&7)];
    g_W0[t]=num_w[node*8+(m&7)];
  }
}
__global__ void k_prep2(const int* __restrict__ adj_all,const float* __restrict__ num_w){
  int t=blockIdx.x*blockDim.x+threadIdx.x;
  if(t<128*3200){
    int b=t/3200,m=t%3200;
    int node=g_IN1[b*400+(m>>3)];
    g_IN2[t]=adj_all[node*8+(m&7)];
    g_W1n[t]=num_w[node*8+(m&7)];
  }
}
__global__ void k_sess(const int* __restrict__ item,const int* __restrict__ mask,
                       const float* __restrict__ emb){
  int b=blockIdx.x,d=threadIdx.x;
  float acc=0.f,ms=0.f;
  for(int l=0;l<50;l++){
    float mv=(float)mask[b*50+l];
    acc+=emb[(size_t)item[b*50+l]*128+d]*mv; ms+=mv;
  }
  g_SESS[b*128+d]=acc/ms;
}

// ---------------- local agg (split ii range across blockIdx.y) -------------
__global__ void __launch_bounds__(256) k_local(const int* __restrict__ inputs,
    const int* __restrict__ adj,const float* __restrict__ emb,
    const float* __restrict__ a_local){
  __shared__ float hs[6400];
  __shared__ float al[512];
  __shared__ float hik[512];
  __shared__ float es[50];
  __shared__ float att[50];
  int b=blockIdx.x,t=threadIdx.x,warp=t>>5,lane=t&31;
  int ii0=blockIdx.y*25, ii1=ii0+25;
  for(int i=t;i<6400;i+=256) hs[i]=emb[(size_t)inputs[b*50+(i>>7)]*128+(i&127)];
  for(int i=t;i<512;i+=256) al[i]=a_local[i];
  __syncthreads();
  for(int ii=ii0;ii<ii1;ii++){
    if(t<128){
      float hv=hs[ii*128+t];
      #pragma unroll
      for(int k=0;k<4;k++) hik[k*128+t]=hv*al[k*128+t];
    }
    __syncthreads();
    for(int jj=warp;jj<50;jj+=8){
      int aj=adj[b*2500+ii*50+jj];
      int k=aj>0?aj-1:0;
      const float4* hk=(const float4*)(hik+k*128);
      const float4* hj=(const float4*)(hs+jj*128);
      float4 p=hk[lane],q=hj[lane];
      float v=p.x*q.x+p.y*q.y+p.z*q.z+p.w*q.w;
      for(int o=16;o;o>>=1) v+=__shfl_xor_sync(0xffffffffu,v,o);
      float e=(aj>0)?(v>0.f?v:0.2f*v):-9e15f;
      if(lane==0) es[jj]=e;
    }
    __syncthreads();
    if(warp==0){
      float m1=-3.4e38f;
      for(int j=lane;j<50;j+=32) m1=fmaxf(m1,es[j]);
      for(int o=16;o;o>>=1) m1=fmaxf(m1,__shfl_xor_sync(0xffffffffu,m1,o));
      float ss=0.f;
      for(int j=lane;j<50;j+=32){ float ex=expf(es[j]-m1); att[j]=ex; ss+=ex; }
      for(int o=16;o;o>>=1) ss+=__shfl_xor_sync(0xffffffffu,ss,o);
      float inv=1.f/ss;
      for(int j=lane;j<50;j+=32) att[j]*=inv;
    }
    __syncthreads();
    if(t<128){
      float acc=0.f;
      for(int j=0;j<50;j++) acc+=att[j]*hs[j*128+t];
      g_HL[(size_t)b*6400+ii*128+t]=acc;
    }
    __syncthreads();
  }
}

// ===== attention core: warp w <-> row m0+w, all 8 samples warp-local =======
#define ATT_COMPUTE(OUTNG,MTOT)                                                \
  {                                                                            \
    __syncwarp();                                                              \
    unsigned long long acc2[8][2];                                             \
    _Pragma("unroll")                                                          \
    for(int ss=0;ss<8;ss++){ acc2[ss][0]=0ull; acc2[ss][1]=0ull; }             \
    for(int e4=0;e4<32;e4++){                                                  \
      ulonglong2 w0 =WT8[(e4*4+0)*32+lane];                                    \
      ulonglong2 w1v=WT8[(e4*4+1)*32+lane];                                    \
      ulonglong2 w2v=WT8[(e4*4+2)*32+lane];                                    \
      ulonglong2 w3v=WT8[(e4*4+3)*32+lane];                                    \
      _Pragma("unroll")                                                        \
      for(int ss=0;ss<8;ss++){                                                 \
        float4 a=NV4[(w*8+ss)*32+e4];                                          \
        unsigned long long ax=f2pack(a.x,a.x);                                 \
        unsigned long long ay=f2pack(a.y,a.y);                                 \
        unsigned long long az=f2pack(a.z,a.z);                                 \
        unsigned long long aw=f2pack(a.w,a.w);                                 \
        ffma2(acc2[ss][0],ax,w0.x);  ffma2(acc2[ss][1],ax,w0.y);               \
        ffma2(acc2[ss][0],ay,w1v.x); ffma2(acc2[ss][1],ay,w1v.y);              \
        ffma2(acc2[ss][0],az,w2v.x); ffma2(acc2[ss][1],az,w2v.y);              \
        ffma2(acc2[ss][0],aw,w3v.x); ffma2(acc2[ss][1],aw,w3v.y);              \
      }                                                                        \
    }                                                                          \
    int d0=lane*4;                                                             \
    float pr[8];                                                               \
    _Pragma("unroll")                                                          \
    for(int ss=0;ss<8;ss++){                                                   \
      float a0,a1,a2,a3;                                                       \
      f2unpack(acc2[ss][0],a0,a1);                                             \
      f2unpack(acc2[ss][1],a2,a3);                                             \
      float nwv=nws[w*8+ss];                                                   \
      float v0=a0+nwv*w129[d0];                                                \
      float v1=a1+nwv*w129[d0+1];                                              \
      float v2=a2+nwv*w129[d0+2];                                              \
      float v3=a3+nwv*w129[d0+3];                                              \
      v0=v0>0.f?v0:0.2f*v0; v1=v1>0.f?v1:0.2f*v1;                              \
      v2=v2>0.f?v2:0.2f*v2; v3=v3>0.f?v3:0.2f*v3;                              \
      float p=v0*g2[d0]+v1*g2[d0+1]+v2*g2[d0+2]+v3*g2[d0+3];                   \
      for(int o=16;o;o>>=1) p+=__shfl_xor_sync(0xffffffffu,p,o);               \
      pr[ss]=p;                                                                \
    }                                                                          \
    float mx=pr[0];                                                            \
    _Pragma("unroll")                                                          \
    for(int i=1;i<8;i++) mx=fmaxf(mx,pr[i]);                                   \
    float exr[8];                                                              \
    _Pragma("unroll")                                                          \
    for(int i=0;i<8;i++) exr[i]=expf(pr[i]-mx);                                \
    float ssum=0.f;                                                            \
    _Pragma("unroll")                                                          \
    for(int i=0;i<8;i++) ssum+=exr[i];                                         \
    float inv=1.f/ssum;                                                        \
    if(m0+w<MTOT){                                                             \
      float o0=0.f,o1=0.f,o2=0.f,o3=0.f;                                       \
      _Pragma("unroll")                                                        \
      for(int i=0;i<8;i++){                                                    \
        float ali=exr[i]*inv;                                                  \
        float4 r=NV4[(w*8+i)*32+lane];                                         \
        o0+=ali*r.x; o1+=ali*r.y; o2+=ali*r.z; o3+=ali*r.w;                    \
      }                                                                        \
      float4 ov; ov.x=o0; ov.y=o1; ov.z=o2; ov.w=o3;                           \
      ((float4*)OUTNG)[((size_t)b*MTOT+(m0+w))*32+lane]=ov;                    \
    }                                                                          \
  }

// ---------------- hop-0 global attention: flattened queue ------------------
__global__ void __launch_bounds__(256) k_att2(int Q,
    const float* __restrict__ emb,const float* __restrict__ gw1h,
    const float* __restrict__ gw2h){
  extern __shared__ float sm[];
  float* wt  = sm;         // 16384 [e][d]
  float* nv  = sm+16384;   // 8192 : 64 rows of 128
  float* w129= sm+24576;   // 128
  float* g2  = sm+24704;   // 128
  float* nws = sm+24832;   // 64
  int t=threadIdx.x,lane=t&31,w=t>>5;
  if(t<128){ w129[t]=gw1h[16384+t]; g2[t]=gw2h[t]; }
  __syncthreads();
  const ulonglong2* WT8=(const ulonglong2*)wt;
  const float4* NV4=(const float4*)nv;
  int g0=blockIdx.x*Q, g1=min(g0+Q,7296);
  int cur_b=-1;
  float4 pfv[8];
  float pfw=0.f;
#define ATT2_PRE(G) do{ \
    int bb=(G)/57, cc=(G)-bb*57; \
    int is1p=(cc>=7); \
    int Mt=is1p?400:50; \
    int mm0=(is1p?(cc-7):cc)*8; \
    const int* ni=is1p?g_IN2:g_IN1; \
    const float* nwq=is1p?g_W1n:g_W0; \
    int mp=min(mm0+w,Mt-1); \
    size_t bp=((size_t)bb*Mt+mp)*8; \
    _Pragma("unroll") \
    for(int ss=0;ss<8;ss++) \
      pfv[ss]=((const float4*)emb)[(size_t)ni[bp+ss]*32+lane]; \
    if(lane<8) pfw=nwq[bp+lane]; \
  }while(0)
  if(g0<g1) ATT2_PRE(g0);
  for(int g=g0;g<g1;g++){
    int b=g/57, c=g-b*57;
    if(b!=cur_b){
      __syncthreads();
      for(int i=t;i<16384;i+=256) wt[i]=g_SESS[b*128+(i>>7)]*gw1h[i];
      cur_b=b;
      __syncthreads();
    }
    int is1=(c>=7);
    int Mtot=is1?400:50;
    int m0=(is1?(c-7):c)*8;
    float* outNG = is1?g_NG1:g_NG0;
    #pragma unroll
    for(int ss=0;ss<8;ss++)
      ((float4*)nv)[(w*8+ss)*32+lane]=pfv[ss];
    if(lane<8) nws[w*8+lane]=pfw;
    if(g+1<g1) ATT2_PRE(g+1);
    ATT_COMPUTE(outNG,Mtot)
  }
#undef ATT2_PRE
}

// ---------------- hop-1 attention (src = g_A1 rows) -------------------------
__global__ void __launch_bounds__(256) k_attm2(int Q,
    const float* __restrict__ gw1h,const float* __restrict__ gw2h){
  extern __shared__ float sm[];
  float* wt  = sm;
  float* nv  = sm+16384;
  float* w129= sm+24576;
  float* g2  = sm+24704;
  float* nws = sm+24832;
  int t=threadIdx.x,lane=t&31,w=t>>5;
  if(t<128){ w129[t]=gw1h[16384+t]; g2[t]=gw2h[t]; }
  __syncthreads();
  const ulonglong2* WT8=(const ulonglong2*)wt;
  const float4* NV4=(const float4*)nv;
  int g0=blockIdx.x*Q, g1=min(g0+Q,896);
  int cur_b=-1;
  float4 pfv[8];
  float pfw=0.f;
#define ATTM_PRE(G) do{ \
    int bb=(G)/7, cc=(G)-bb*7; \
    int mp=min(cc*8+w,49); \
    size_t bp=((size_t)bb*50+mp)*8; \
    _Pragma("unroll") \
    for(int ss=0;ss<8;ss++) \
      pfv[ss]=((const float4*)g_A1)[(bp+ss)*32+lane]; \
    if(lane<8) pfw=g_W0[bp+lane]; \
  }while(0)
  if(g0<g1) ATTM_PRE(g0);
  for(int g=g0;g<g1;g++){
    int b=g/7, c=g-b*7;
    if(b!=cur_b){
      __syncthreads();
      for(int i=t;i<16384;i+=256) wt[i]=g_SESS[b*128+(i>>7)]*gw1h[i];
      cur_b=b;
      __syncthreads();
    }
    const int Mtot=50;
    int m0=c*8;
    #pragma unroll
    for(int ss=0;ss<8;ss++)
      ((float4*)nv)[(w*8+ss)*32+lane]=pfv[ss];
    if(lane<8) nws[w*8+lane]=pfw;
    if(g+1<g1) ATTM_PRE(g+1);
    ATT_COMPUTE(g_NG0,Mtot)
  }
#undef ATTM_PRE
}

// -------- linear (concat 256 -> 128), persistent, FFMA2, double-buffered ---
// Gather remap: thread owns (row = t&31, e-block = (t>>5)*32..+31) -> 8 LDG.128
// instead of 32 scattered LDG.32. inT content identical -> bitwise-same output.
// cfg2 additionally writes outmix = g_HL + relu(v)  (fused k_mix)
__global__ void __launch_bounds__(256) k_lin(int nrows,int cfg,
    const int* __restrict__ idxtab,const float* __restrict__ extA,
    const float* __restrict__ extB,const float* __restrict__ w,
    float* __restrict__ outmix){
  extern __shared__ float sm[];
  float* ws=sm;          // 32768 [e][d]
  float* inT=sm+32768;   // 8192 [e][32]
  int t=threadIdx.x;
  for(int i=t;i<32768;i+=256) ws[i]=w[i];
  int ngroups=(nrows+31)>>5;
  float* outp=(cfg==0)?g_A0:(cfg==1)?g_A1:(cfg==2)?g_HG:g_NH;
  float pf[32];
  int grp=blockIdx.x;
  int rL=t&31, wq=t>>5;      // row lane, e-warp
  int ebase=wq*32;

#define LIN_LOAD_PF(GRP) do{ \
    int row=(GRP)*32+rL; \
    if(row<nrows){ \
      if(ebase<128){ \
        size_t off; \
        const float* basep; \
        if(cfg==0){ off=(size_t)idxtab[row]*128; basep=extA; } \
        else if(cfg==1){ off=(size_t)g_IN1[row]*128; basep=extA; } \
        else if(cfg==2){ off=(size_t)row*128; basep=g_A0; } \
        else { off=(size_t)(row%50)*128; basep=extA; } \
        _Pragma("unroll") \
        for(int j4=0;j4<8;j4++) \
          *(float4*)&pf[j4*4]=*(const float4*)&basep[off+ebase+j4*4]; \
      }else{ \
        int e2b=ebase-128; \
        const float* basep; \
        if(cfg==0)      basep=g_NG0; \
        else if(cfg==1) basep=g_NG1; \
        else if(cfg==2) basep=g_NG0; \
        else            basep=extB; \
        _Pragma("unroll") \
        for(int j4=0;j4<8;j4++) \
          *(float4*)&pf[j4*4]=*(const float4*)&basep[(size_t)row*128+e2b+j4*4]; \
      } \
    }else{ \
      _Pragma("unroll") \
      for(int k=0;k<32;k++) pf[k]=0.f; \
    } \
  }while(0)

  if(grp<ngroups) LIN_LOAD_PF(grp);
  for(;grp<ngroups;grp+=gridDim.x){
    __syncthreads();
    #pragma unroll
    for(int j=0;j<32;j++) inT[(ebase+j)*32+rL]=pf[j];
    __syncthreads();
    int nxt=grp+gridDim.x;
    if(nxt<ngroups) LIN_LOAD_PF(nxt);
    int row0=grp*32;
    int d=t&127,rh=t>>7;
    unsigned long long acc2[8];
    #pragma unroll
    for(int q=0;q<8;q++) acc2[q]=0ull;
    const ulonglong2* I8=(const ulonglong2*)inT;
    #pragma unroll 8
    for(int e=0;e<256;e++){
      float wv=ws[e*128+d];
      unsigned long long wv2=f2pack(wv,wv);
      ulonglong2 u0=I8[e*8+rh*4+0];
      ulonglong2 u1=I8[e*8+rh*4+1];
      ulonglong2 u2=I8[e*8+rh*4+2];
      ulonglong2 u3=I8[e*8+rh*4+3];
      ffma2(acc2[0],wv2,u0.x); ffma2(acc2[1],wv2,u0.y);
      ffma2(acc2[2],wv2,u1.x); ffma2(acc2[3],wv2,u1.y);
      ffma2(acc2[4],wv2,u2.x); ffma2(acc2[5],wv2,u2.y);
      ffma2(acc2[6],wv2,u3.x); ffma2(acc2[7],wv2,u3.y);
    }
    #pragma unroll
    for(int q=0;q<8;q++){
      float lo,hi;
      f2unpack(acc2[q],lo,hi);
      int rlo=row0+rh*16+q*2;
      if(rlo<nrows){
        float v=(cfg==3)?tanhf(lo):fmaxf(lo,0.f);
        outp[(size_t)rlo*128+d]=v;
        if(cfg==2) outmix[(size_t)rlo*128+d]=g_HL[(size_t)rlo*128+d]+v;
      }
      if(rlo+1<nrows){
        float v=(cfg==3)?tanhf(hi):fmaxf(hi,0.f);
        outp[(size_t)(rlo+1)*128+d]=v;
        if(cfg==2) outmix[(size_t)(rlo+1)*128+d]=g_HL[(size_t)(rlo+1)*128+d]+v;
      }
    }
  }
#undef LIN_LOAD_PF
}

// ---------------- ssl ----------------
__global__ void k_ssl(){
  __shared__ float red[128];
  int b=blockIdx.x,t=threadIdx.x;
  int pb=g_PR[b];
  float pos=0.f,neg=0.f;
  for(int l=0;l<50;l++){
    float hl=g_HL[(size_t)b*6400+l*128+t];
    float hg=g_HG[(size_t)b*6400+l*128+t];
    pos+=hl*hg;
    neg+=hg*g_HL[(size_t)pb*6400+g_PC[l]*128+t];
  }
  float sp=1.f/(1.f+expf(-pos)),sn=1.f/(1.f+expf(-neg));
  float term=-logf(1e-8f+sp)-logf(1e-8f+1.f-sn);
  red[t]=term; __syncthreads();
  for(int o=64;o;o>>=1){ if(t<o) red[t]+=red[t+o]; __syncthreads(); }
  if(t==0) g_LP[b]=red[0];
}
__global__ void k_fin(float* __restrict__ out){
  __shared__ float r[128];
  int t=threadIdx.x;
  r[t]=g_LP[t]; __syncthreads();
  for(int o=64;o;o>>=1){ if(t<o) r[t]+=r[t+o]; __syncthreads(); }
  if(t==0) out[819200]=0.005f*r[0];
}

// ---------------- glu/select ----------------
__global__ void __launch_bounds__(256) k_glu(const float* __restrict__ hidden,
    const int* __restrict__ mask,const float* __restrict__ glu1w,
    const float* __restrict__ glu1b,const float* __restrict__ glu2w,
    const float* __restrict__ w2){
  extern __shared__ float sm[];
  float* g1t=sm;        // 16384 [e][d]
  float* hS =sm+16384;  // 6400
  float* nhS=sm+22784;  // 6400
  float* hs =sm+29184;  // 128
  float* t2 =sm+29312;  // 128
  float* bet=sm+29440;  // 64
  float* w2s=sm+29504;  // 128
  float* b1s=sm+29632;  // 128
  int b=blockIdx.x,t=threadIdx.x,warp=t>>5,lane=t&31;
  for(int i=t;i<16384;i+=256){ int e=i>>7,d=i&127; g1t[i]=glu1w[d*128+e]; }
  for(int i=t;i<6400;i+=256){ hS[i]=hidden[(size_t)b*6400+i]; nhS[i]=g_NH[(size_t)b*6400+i]; }
  if(t<128){ w2s[t]=w2[t]; b1s[t]=glu1b[t]; }
  __syncthreads();
  if(t<128){
    float a=0.f,ms=0.f;
    for(int l=0;l<50;l++){ float mv=(float)mask[b*50+l]; a+=hS[l*128+t]*mv; ms+=mv; }
    hs[t]=a/ms;
  }
  __syncthreads();
  if(t<128){
    float a=0.f;
    for(int e=0;e<128;e++) a+=hs[e]*glu2w[t*128+e];
    t2[t]=a;
  }
  __syncthreads();
  const float4* G14=(const float4*)g1t;
  for(int lb=0;lb<56;lb+=8){
    int l=lb+warp;
    if(l<50){
      const float4* N4=(const float4*)(nhS+l*128);
      float a0=0,a1=0,a2=0,a3=0;
      #pragma unroll 4
      for(int e4=0;e4<32;e4++){
        float4 a=N4[e4];
        float4 w=G14[(e4*4+0)*32+lane];
        a0+=a.x*w.x; a1+=a.x*w.y; a2+=a.x*w.z; a3+=a.x*w.w;
        w=G14[(e4*4+1)*32+lane];
        a0+=a.y*w.x; a1+=a.y*w.y; a2+=a.y*w.z; a3+=a.y*w.w;
        w=G14[(e4*4+2)*32+lane];
        a0+=a.z*w.x; a1+=a.z*w.y; a2+=a.z*w.z; a3+=a.z*w.w;
        w=G14[(e4*4+3)*32+lane];
        a0+=a.w*w.x; a1+=a.w*w.y; a2+=a.w*w.z; a3+=a.w*w.w;
      }
      int d0=lane*4;
      a0=1.f/(1.f+expf(-(a0+b1s[d0]+t2[d0])));
      a1=1.f/(1.f+expf(-(a1+b1s[d0+1]+t2[d0+1])));
      a2=1.f/(1.f+expf(-(a2+b1s[d0+2]+t2[d0+2])));
      a3=1.f/(1.f+expf(-(a3+b1s[d0+3]+t2[d0+3])));
      float p=a0*w2s[d0]+a1*w2s[d0+1]+a2*w2s[d0+2]+a3*w2s[d0+3];
      for(int o=16;o;o>>=1) p+=__shfl_xor_sync(0xffffffffu,p,o);
      if(lane==0) bet[l]=p*(float)mask[b*50+l];
    }
  }
  __syncthreads();
  if(t<128){
    float a=0.f;
    for(int l=0;l<50;l++) a+=bet[l]*hS[l*128+t];
    g_SEL[b*128+t]=a;
  }
}

// ---------------- neighbor top-k ----------------
__global__ void __launch_bounds__(128) k_nbr(){
  extern __shared__ float sm[];
  float* sel=sm;  // 16384
  __shared__ float nrm[128];
  __shared__ float ev[128];
  __shared__ float tv[9];
  __shared__ int   ti[9];
  __shared__ float red[4];
  int b=blockIdx.x,t=threadIdx.x;
  for(int i=t;i<16384;i+=128) sel[i]=g_SEL[i];
  __syncthreads();
  { float a=0.f;
    for(int d=0;d<128;d++){ float v=sel[t*128+d]; a+=v*v; }
    nrm[t]=sqrtf(a+128e-6f); }
  __syncthreads();
  float dot=0.f;
  for(int d=0;d<128;d++) dot+=sel[b*128+d]*sel[t*128+d];
  float e=dot/(nrm[b]*nrm[t]);
  float mx=e;
  for(int o=16;o;o>>=1) mx=fmaxf(mx,__shfl_xor_sync(0xffffffffu,mx,o));
  if((t&31)==0) red[t>>5]=mx;
  __syncthreads();
  mx=fmaxf(fmaxf(red[0],red[1]),fmaxf(red[2],red[3]));
  float ex=expf(e-mx);
  float ss=ex;
  for(int o=16;o;o>>=1) ss+=__shfl_xor_sync(0xffffffffu,ss,o);
  __syncthreads();
  if((t&31)==0) red[t>>5]=ss;
  __syncthreads();
  ss=red[0]+red[1]+red[2]+red[3];
  ev[t]=ex/ss;
  __syncthreads();
  if(t==0){
    for(int k=0;k<9;k++){
      float bv=-1.f; int bi=0;
      for(int j=0;j<128;j++) if(ev[j]>bv){ bv=ev[j]; bi=j; }
      tv[k]=bv; ti[k]=bi; ev[bi]=-2.f;
    }
    float m2=tv[0],s2=0.f;
    for(int k=0;k<9;k++){ tv[k]=expf(tv[k]-m2); s2+=tv[k]; }
    float inv=1.f/s2;
    for(int k=0;k<9;k++) tv[k]*=inv;
  }
  __syncthreads();
  float nb=0.f;
  #pragma unroll
  for(int k=0;k<9;k++) nb+=tv[k]*sel[ti[k]*128+t];
  g_SEL2T[t*128+b]=sel[b*128+t]+nb;
}

// ---------------- scores GEMM (FFMA2, 64-j tiles, 2 blocks/SM) --------------
__global__ void __launch_bounds__(256) k_scores(const float* __restrict__ emb,
                                                float* __restrict__ outp){
  extern __shared__ float sm[];
  float* selT=sm;        // 16384 [e][b]
  float* embT=sm+16384;  // 128*65 [e][j] stride 65 (64 j per tile)
  int t=threadIdx.x;
  int j0=blockIdx.x*64;
  for(int i=t;i<16384;i+=256) selT[i]=g_SEL2T[i];
  for(int i=t;i<8192;i+=256){
    int j=i&63,e=i>>6;
    int node=1+j0+j;
    embT[e*65+j]=(node<100000)?emb[(size_t)node*128+e]:0.f;
  }
  __syncthreads();
  int j=t&63,bh=(t>>6)&3;
  unsigned long long acc2[16];
  #pragma unroll
  for(int q=0;q<16;q++) acc2[q]=0ull;
  const ulonglong2* S8=(const ulonglong2*)selT;
  #pragma unroll 2
  for(int e=0;e<128;e++){
    float evv=embT[e*65+j];
    unsigned long long ev2=f2pack(evv,evv);
    const ulonglong2* s=&S8[e*32+bh*8];
    #pragma unroll
    for(int q=0;q<8;q++){
      ulonglong2 u=s[q];
      ffma2(acc2[q*2+0],ev2,u.x);
      ffma2(acc2[q*2+1],ev2,u.y);
    }
  }
  if(j0+j<99999){
    #pragma unroll
    for(int q=0;q<16;q++){
      float lo,hi;
      f2unpack(acc2[q],lo,hi);
      int b=bh*32+q*2;
      outp[(size_t)b*99999+j0+j]=lo;
      outp[(size_t)(b+1)*99999+j0+j]=hi;
    }
  }
}

// ---------------- launch ----------------
extern "C" void kernel_launch(void* const* d_in,const int* in_sizes,int n_in,
                              void* d_out,int out_size){
  const int*   inputs =(const int*)d_in[0];
  const int*   adj    =(const int*)d_in[1];
  const int*   mask   =(const int*)d_in[2];
  const int*   item   =(const int*)d_in[3];
  const int*   adj_all=(const int*)d_in[5];
  const float* num_w  =(const float*)d_in[6];
  const float* emb    =(const float*)d_in[7];
  const float* pos    =(const float*)d_in[8];
  const float* a_local=(const float*)d_in[9];
  const float* gw1    =(const float*)d_in[10];
  const float* gw2    =(const float*)d_in[11];
  const float* gw3    =(const float*)d_in[12];
  const float* w1     =(const float*)d_in[13];
  const float* w2     =(const float*)d_in[14];
  const float* g1w    =(const float*)d_in[15];
  const float* g1b    =(const float*)d_in[16];
  const float* g2w    =(const float*)d_in[17];
  float* out=(float*)d_out;

  const size_t SM_ATT=24896u*4u;   // 99,584 B -> 2 blocks/SM
  const size_t SM_LIN=40960u*4u;   // 163,840 B -> 1 block/SM
  const size_t SM_GLU=29760u*4u;
  const size_t SM_SC =24704u*4u;   // 98,816 B -> 2 blocks/SM
  const size_t SM_NBR=16384u*4u;
  cudaFuncSetAttribute(k_att2,  cudaFuncAttributeMaxDynamicSharedMemorySize,(int)SM_ATT);
  cudaFuncSetAttribute(k_attm2, cudaFuncAttributeMaxDynamicSharedMemorySize,(int)SM_ATT);
  cudaFuncSetAttribute(k_lin,   cudaFuncAttributeMaxDynamicSharedMemorySize,(int)SM_LIN);
  cudaFuncSetAttribute(k_glu,   cudaFuncAttributeMaxDynamicSharedMemorySize,(int)SM_GLU);
  cudaFuncSetAttribute(k_scores,cudaFuncAttributeMaxDynamicSharedMemorySize,(int)SM_SC);
  cudaFuncSetAttribute(k_nbr,   cudaFuncAttributeMaxDynamicSharedMemorySize,(int)SM_NBR);

  k_prep1<<<200,256>>>(inputs,adj_all,num_w);
  k_prep2<<<1600,256>>>(adj_all,num_w);
  k_sess<<<128,128>>>(item,mask,emb);
  // hop 0: flattened mode0+mode1 attention (7296 chunks over 296 resident blocks)
  k_att2<<<296,256,SM_ATT>>>(25,emb,gw1,gw2);                        // -> g_NG0, g_NG1
  k_perm<<<1,128>>>();
  k_local<<<dim3(128,2),256>>>(inputs,adj,emb,a_local);
  k_lin<<<148,256,SM_LIN>>>(6400,0,inputs,emb,0,gw3,0);              // -> g_A0
  k_lin<<<148,256,SM_LIN>>>(51200,1,0,emb,0,gw3,0);                  // -> g_A1
  // hop 1 (896 chunks over 224 blocks = 1 wave)
  k_attm2<<<224,256,SM_ATT>>>(4,gw1+129*128,gw2+128);                // -> g_NG0
  k_lin<<<148,256,SM_LIN>>>(6400,2,0,0,0,gw3+256*128,out);           // -> g_HG + out (fused mix)
  // outputs
  k_ssl<<<128,128>>>();
  k_fin<<<1,128>>>(out);
  // scores head
  k_lin<<<148,256,SM_LIN>>>(6400,3,0,pos,out,w1,0);                  // -> g_NH
  k_glu<<<128,256,SM_GLU>>>(out,mask,g1w,g1b,g2w,w2);
  k_nbr<<<128,128,SM_NBR>>>();
  k_scores<<<1563,256,SM_SC>>>(emb,out+819201);
}

// round 17
// speedup vs baseline: 1.1653x; 1.0003x over previous
#include <cuda_runtime.h>
#include <math.h>

// ---------------- f32x2 packed-FMA helpers (bitwise = 2x IEEE fp32 FMA) ----
__device__ __forceinline__ unsigned long long f2pack(float x,float y){
  unsigned long long r;
  asm("mov.b64 %0,{%1,%2};":"=l"(r):"r"(__float_as_uint(x)),"r"(__float_as_uint(y)));
  return r;
}
__device__ __forceinline__ void f2unpack(unsigned long long v,float&x,float&y){
  unsigned ux,uy;
  asm("mov.b64 {%0,%1},%2;":"=r"(ux),"=r"(uy):"l"(v));
  x=__uint_as_float(ux); y=__uint_as_float(uy);
}
__device__ __forceinline__ void ffma2(unsigned long long&d,unsigned long long a,unsigned long long b){
  asm("fma.rn.f32x2 %0,%1,%2,%0;":"+l"(d):"l"(a),"l"(b));
}

// ---------------- scratch ----------------
__device__ float g_SESS[128*128];
__device__ int   g_IN1[128*400];
__device__ float g_W0 [128*400];
__device__ int   g_IN2[128*3200];
__device__ float g_W1n[128*3200];
__device__ float g_NG0[128*50*128];
__device__ float g_NG1[128*400*128];
__device__ float g_A0 [128*50*128];
__device__ float g_A1 [128*400*128];
__device__ float g_HL [128*50*128];
__device__ float g_HG [128*50*128];
__device__ float g_NH [128*50*128];
__device__ float g_SEL[128*128];
__device__ float g_SEL2T[128*128];
__device__ float g_LP[128];
__device__ int   g_PR[128];
__device__ int   g_PC[64];

// ---------------- threefry ----------------
__device__ __forceinline__ void tf(unsigned k0,unsigned k1,unsigned x0,unsigned x1,
                                   unsigned&o0,unsigned&o1){
  unsigned ks2=k0^k1^0x1BD11BDAu;
  x0+=k0; x1+=k1;
#define RND(r) {x0+=x1; x1=(x1<<(r))|(x1>>(32-(r))); x1^=x0;}
  RND(13)RND(15)RND(26)RND(6)   x0+=k1;  x1+=ks2+1u;
  RND(17)RND(29)RND(16)RND(24)  x0+=ks2; x1+=k0+2u;
  RND(13)RND(15)RND(26)RND(6)   x0+=k0;  x1+=k1+3u;
  RND(17)RND(29)RND(16)RND(24)  x0+=k1;  x1+=ks2+4u;
  RND(13)RND(15)RND(26)RND(6)   x0+=ks2; x1+=k0+5u;
#undef RND
  o0=x0; o1=x1;
}

__global__ void k_perm(){
  __shared__ unsigned keys[4];
  __shared__ unsigned br[128];
  __shared__ unsigned bc[64];
  int t=threadIdx.x;
  if(t==0){
    unsigned u0,u1,v0,v1,p0,p1,q0,q1;
    tf(0u,42u,0u,2u,u0,u1); tf(0u,42u,1u,3u,v0,v1);
    unsigned kr0=u0,kr1=v0,kc0=u1,kc1=v1;
    tf(kr0,kr1,0u,2u,p0,p1); tf(kr0,kr1,1u,3u,q0,q1);
    keys[0]=p1; keys[1]=q1;
    tf(kc0,kc1,0u,2u,p0,p1); tf(kc0,kc1,1u,3u,q0,q1);
    keys[2]=p1; keys[3]=q1;
  }
  __syncthreads();
  { int j=t&63; unsigned w0,w1;
    tf(keys[0],keys[1],(unsigned)j,(unsigned)(j+64),w0,w1);
    br[t]=(t<64)?w0:w1; }
  if(t<50){ int j=(t<25)?t:t-25; unsigned w0,w1;
    tf(keys[2],keys[3],(unsigned)j,(unsigned)(j+25),w0,w1);
    bc[t]=(t<25)?w0:w1; }
  __syncthreads();
  { unsigned mine=br[t]; int r=0;
    for(int j=0;j<128;j++){ unsigned bj=br[j]; r+=(bj<mine)||(bj==mine&&j<t); }
    g_PR[r]=t; }
  if(t<50){ unsigned mine=bc[t]; int r=0;
    for(int j=0;j<50;j++){ unsigned bj=bc[j]; r+=(bj<mine)||(bj==mine&&j<t); }
    g_PC[r]=t; }
}

// ---------------- prep ----------------
__global__ void k_prep1(const int* __restrict__ inputs,const int* __restrict__ adj_all,
                        const float* __restrict__ num_w){
  int t=blockIdx.x*blockDim.x+threadIdx.x;
  if(t<128*400){
    int b=t/400,m=t%400;
    int node=inputs[b*50+(m>>3)];
    g_IN1[t]=adj_all[node*8+(m&7)];
    g_W0[t]=num_w[node*8+(m&7)];
  }
}
__global__ void k_prep2(const int* __restrict__ adj_all,const float* __restrict__ num_w){
  int t=blockIdx.x*blockDim.x+threadIdx.x;
  if(t<128*3200){
    int b=t/3200,m=t%3200;
    int node=g_IN1[b*400+(m>>3)];
    g_IN2[t]=adj_all[node*8+(m&7)];
    g_W1n[t]=num_w[node*8+(m&7)];
  }
}
__global__ void k_sess(const int* __restrict__ item,const int* __restrict__ mask,
                       const float* __restrict__ emb){
  int b=blockIdx.x,d=threadIdx.x;
  float acc=0.f,ms=0.f;
  for(int l=0;l<50;l++){
    float mv=(float)mask[b*50+l];
    acc+=emb[(size_t)item[b*50+l]*128+d]*mv; ms+=mv;
  }
  g_SESS[b*128+d]=acc/ms;
}

// ---------------- local agg (split ii range across blockIdx.y) -------------
__global__ void __launch_bounds__(256) k_local(const int* __restrict__ inputs,
    const int* __restrict__ adj,const float* __restrict__ emb,
    const float* __restrict__ a_local){
  __shared__ float hs[6400];
  __shared__ float al[512];
  __shared__ float hik[512];
  __shared__ float es[50];
  __shared__ float att[50];
  int b=blockIdx.x,t=threadIdx.x,warp=t>>5,lane=t&31;
  int ii0=blockIdx.y*25, ii1=ii0+25;
  for(int i=t;i<6400;i+=256) hs[i]=emb[(size_t)inputs[b*50+(i>>7)]*128+(i&127)];
  for(int i=t;i<512;i+=256) al[i]=a_local[i];
  __syncthreads();
  for(int ii=ii0;ii<ii1;ii++){
    if(t<128){
      float hv=hs[ii*128+t];
      #pragma unroll
      for(int k=0;k<4;k++) hik[k*128+t]=hv*al[k*128+t];
    }
    __syncthreads();
    for(int jj=warp;jj<50;jj+=8){
      int aj=adj[b*2500+ii*50+jj];
      int k=aj>0?aj-1:0;
      const float4* hk=(const float4*)(hik+k*128);
      const float4* hj=(const float4*)(hs+jj*128);
      float4 p=hk[lane],q=hj[lane];
      float v=p.x*q.x+p.y*q.y+p.z*q.z+p.w*q.w;
      for(int o=16;o;o>>=1) v+=__shfl_xor_sync(0xffffffffu,v,o);
      float e=(aj>0)?(v>0.f?v:0.2f*v):-9e15f;
      if(lane==0) es[jj]=e;
    }
    __syncthreads();
    if(warp==0){
      float m1=-3.4e38f;
      for(int j=lane;j<50;j+=32) m1=fmaxf(m1,es[j]);
      for(int o=16;o;o>>=1) m1=fmaxf(m1,__shfl_xor_sync(0xffffffffu,m1,o));
      float ss=0.f;
      for(int j=lane;j<50;j+=32){ float ex=expf(es[j]-m1); att[j]=ex; ss+=ex; }
      for(int o=16;o;o>>=1) ss+=__shfl_xor_sync(0xffffffffu,ss,o);
      float inv=1.f/ss;
      for(int j=lane;j<50;j+=32) att[j]*=inv;
    }
    __syncthreads();
    if(t<128){
      float acc=0.f;
      for(int j=0;j<50;j++) acc+=att[j]*hs[j*128+t];
      g_HL[(size_t)b*6400+ii*128+t]=acc;
    }
    __syncthreads();
  }
}

// ===== attention core: warp w <-> row m0+w, all 8 samples warp-local =======
#define ATT_COMPUTE(OUTNG,MTOT)                                                \
  {                                                                            \
    __syncwarp();                                                              \
    unsigned long long acc2[8][2];                                             \
    _Pragma("unroll")                                                          \
    for(int ss=0;ss<8;ss++){ acc2[ss][0]=0ull; acc2[ss][1]=0ull; }             \
    for(int e4=0;e4<32;e4++){                                                  \
      ulonglong2 w0 =WT8[(e4*4+0)*32+lane];                                    \
      ulonglong2 w1v=WT8[(e4*4+1)*32+lane];                                    \
      ulonglong2 w2v=WT8[(e4*4+2)*32+lane];                                    \
      ulonglong2 w3v=WT8[(e4*4+3)*32+lane];                                    \
      _Pragma("unroll")                                                        \
      for(int ss=0;ss<8;ss++){                                                 \
        float4 a=NV4[(w*8+ss)*32+e4];                                          \
        unsigned long long ax=f2pack(a.x,a.x);                                 \
        unsigned long long ay=f2pack(a.y,a.y);                                 \
        unsigned long long az=f2pack(a.z,a.z);                                 \
        unsigned long long aw=f2pack(a.w,a.w);                                 \
        ffma2(acc2[ss][0],ax,w0.x);  ffma2(acc2[ss][1],ax,w0.y);               \
        ffma2(acc2[ss][0],ay,w1v.x); ffma2(acc2[ss][1],ay,w1v.y);              \
        ffma2(acc2[ss][0],az,w2v.x); ffma2(acc2[ss][1],az,w2v.y);              \
        ffma2(acc2[ss][0],aw,w3v.x); ffma2(acc2[ss][1],aw,w3v.y);              \
      }                                                                        \
    }                                                                          \
    int d0=lane*4;                                                             \
    float pr[8];                                                               \
    _Pragma("unroll")                                                          \
    for(int ss=0;ss<8;ss++){                                                   \
      float a0,a1,a2,a3;                                                       \
      f2unpack(acc2[ss][0],a0,a1);                                             \
      f2unpack(acc2[ss][1],a2,a3);                                             \
      float nwv=nws[w*8+ss];                                                   \
      float v0=a0+nwv*w129[d0];                                                \
      float v1=a1+nwv*w129[d0+1];                                              \
      float v2=a2+nwv*w129[d0+2];                                              \
      float v3=a3+nwv*w129[d0+3];                                              \
      v0=v0>0.f?v0:0.2f*v0; v1=v1>0.f?v1:0.2f*v1;                              \
      v2=v2>0.f?v2:0.2f*v2; v3=v3>0.f?v3:0.2f*v3;                              \
      float p=v0*g2[d0]+v1*g2[d0+1]+v2*g2[d0+2]+v3*g2[d0+3];                   \
      for(int o=16;o;o>>=1) p+=__shfl_xor_sync(0xffffffffu,p,o);               \
      pr[ss]=p;                                                                \
    }                                                                          \
    float mx=pr[0];                                                            \
    _Pragma("unroll")                                                          \
    for(int i=1;i<8;i++) mx=fmaxf(mx,pr[i]);                                   \
    float exr[8];                                                              \
    _Pragma("unroll")                                                          \
    for(int i=0;i<8;i++) exr[i]=expf(pr[i]-mx);                                \
    float ssum=0.f;                                                            \
    _Pragma("unroll")                                                          \
    for(int i=0;i<8;i++) ssum+=exr[i];                                         \
    float inv=1.f/ssum;                                                        \
    if(m0+w<MTOT){                                                             \
      float o0=0.f,o1=0.f,o2=0.f,o3=0.f;                                       \
      _Pragma("unroll")                                                        \
      for(int i=0;i<8;i++){                                                    \
        float ali=exr[i]*inv;                                                  \
        float4 r=NV4[(w*8+i)*32+lane];                                         \
        o0+=ali*r.x; o1+=ali*r.y; o2+=ali*r.z; o3+=ali*r.w;                    \
      }                                                                        \
      float4 ov; ov.x=o0; ov.y=o1; ov.z=o2; ov.w=o3;                           \
      ((float4*)OUTNG)[((size_t)b*MTOT+(m0+w))*32+lane]=ov;                    \
    }                                                                          \
  }

// ---------------- hop-0 global attention: flattened queue ------------------
__global__ void __launch_bounds__(256) k_att2(int Q,
    const float* __restrict__ emb,const float* __restrict__ gw1h,
    const float* __restrict__ gw2h){
  extern __shared__ float sm[];
  float* wt  = sm;         // 16384 [e][d]
  float* nv  = sm+16384;   // 8192 : 64 rows of 128
  float* w129= sm+24576;   // 128
  float* g2  = sm+24704;   // 128
  float* nws = sm+24832;   // 64
  int t=threadIdx.x,lane=t&31,w=t>>5;
  if(t<128){ w129[t]=gw1h[16384+t]; g2[t]=gw2h[t]; }
  __syncthreads();
  const ulonglong2* WT8=(const ulonglong2*)wt;
  const float4* NV4=(const float4*)nv;
  int g0=blockIdx.x*Q, g1=min(g0+Q,7296);
  int cur_b=-1;
  float4 pfv[8];
  float pfw=0.f;
#define ATT2_PRE(G) do{ \
    int bb=(G)/57, cc=(G)-bb*57; \
    int is1p=(cc>=7); \
    int Mt=is1p?400:50; \
    int mm0=(is1p?(cc-7):cc)*8; \
    const int* ni=is1p?g_IN2:g_IN1; \
    const float* nwq=is1p?g_W1n:g_W0; \
    int mp=min(mm0+w,Mt-1); \
    size_t bp=((size_t)bb*Mt+mp)*8; \
    _Pragma("unroll") \
    for(int ss=0;ss<8;ss++) \
      pfv[ss]=((const float4*)emb)[(size_t)ni[bp+ss]*32+lane]; \
    if(lane<8) pfw=nwq[bp+lane]; \
  }while(0)
  if(g0<g1) ATT2_PRE(g0);
  for(int g=g0;g<g1;g++){
    int b=g/57, c=g-b*57;
    if(b!=cur_b){
      __syncthreads();
      for(int i=t;i<16384;i+=256) wt[i]=g_SESS[b*128+(i>>7)]*gw1h[i];
      cur_b=b;
      __syncthreads();
    }
    int is1=(c>=7);
    int Mtot=is1?400:50;
    int m0=(is1?(c-7):c)*8;
    float* outNG = is1?g_NG1:g_NG0;
    #pragma unroll
    for(int ss=0;ss<8;ss++)
      ((float4*)nv)[(w*8+ss)*32+lane]=pfv[ss];
    if(lane<8) nws[w*8+lane]=pfw;
    if(g+1<g1) ATT2_PRE(g+1);
    ATT_COMPUTE(outNG,Mtot)
  }
#undef ATT2_PRE
}

// ---------------- hop-1 attention (src = g_A1 rows) -------------------------
__global__ void __launch_bounds__(256) k_attm2(int Q,
    const float* __restrict__ gw1h,const float* __restrict__ gw2h){
  extern __shared__ float sm[];
  float* wt  = sm;
  float* nv  = sm+16384;
  float* w129= sm+24576;
  float* g2  = sm+24704;
  float* nws = sm+24832;
  int t=threadIdx.x,lane=t&31,w=t>>5;
  if(t<128){ w129[t]=gw1h[16384+t]; g2[t]=gw2h[t]; }
  __syncthreads();
  const ulonglong2* WT8=(const ulonglong2*)wt;
  const float4* NV4=(const float4*)nv;
  int g0=blockIdx.x*Q, g1=min(g0+Q,896);
  int cur_b=-1;
  float4 pfv[8];
  float pfw=0.f;
#define ATTM_PRE(G) do{ \
    int bb=(G)/7, cc=(G)-bb*7; \
    int mp=min(cc*8+w,49); \
    size_t bp=((size_t)bb*50+mp)*8; \
    _Pragma("unroll") \
    for(int ss=0;ss<8;ss++) \
      pfv[ss]=((const float4*)g_A1)[(bp+ss)*32+lane]; \
    if(lane<8) pfw=g_W0[bp+lane]; \
  }while(0)
  if(g0<g1) ATTM_PRE(g0);
  for(int g=g0;g<g1;g++){
    int b=g/7, c=g-b*7;
    if(b!=cur_b){
      __syncthreads();
      for(int i=t;i<16384;i+=256) wt[i]=g_SESS[b*128+(i>>7)]*gw1h[i];
      cur_b=b;
      __syncthreads();
    }
    const int Mtot=50;
    int m0=c*8;
    #pragma unroll
    for(int ss=0;ss<8;ss++)
      ((float4*)nv)[(w*8+ss)*32+lane]=pfv[ss];
    if(lane<8) nws[w*8+lane]=pfw;
    if(g+1<g1) ATTM_PRE(g+1);
    ATT_COMPUTE(g_NG0,Mtot)
  }
#undef ATTM_PRE
}

// -------- linear (concat 256 -> 128), persistent, FFMA2, double-buffered ---
__global__ void __launch_bounds__(256) k_lin(int nrows,int cfg,
    const int* __restrict__ idxtab,const float* __restrict__ extA,
    const float* __restrict__ extB,const float* __restrict__ w,
    float* __restrict__ outmix){
  extern __shared__ float sm[];
  float* ws=sm;          // 32768 [e][d]
  float* inT=sm+32768;   // 8192 [e][32]
  int t=threadIdx.x;
  for(int i=t;i<32768;i+=256) ws[i]=w[i];
  int ngroups=(nrows+31)>>5;
  float* outp=(cfg==0)?g_A0:(cfg==1)?g_A1:(cfg==2)?g_HG:g_NH;
  float pf[32];
  int grp=blockIdx.x;
  int rL=t&31, wq=t>>5;
  int ebase=wq*32;

#define LIN_LOAD_PF(GRP) do{ \
    int row=(GRP)*32+rL; \
    if(row<nrows){ \
      if(ebase<128){ \
        size_t off; \
        const float* basep; \
        if(cfg==0){ off=(size_t)idxtab[row]*128; basep=extA; } \
        else if(cfg==1){ off=(size_t)g_IN1[row]*128; basep=extA; } \
        else if(cfg==2){ off=(size_t)row*128; basep=g_A0; } \
        else { off=(size_t)(row%50)*128; basep=extA; } \
        _Pragma("unroll") \
        for(int j4=0;j4<8;j4++) \
          *(float4*)&pf[j4*4]=*(const float4*)&basep[off+ebase+j4*4]; \
      }else{ \
        int e2b=ebase-128; \
        const float* basep; \
        if(cfg==0)      basep=g_NG0; \
        else if(cfg==1) basep=g_NG1; \
        else if(cfg==2) basep=g_NG0; \
        else            basep=extB; \
        _Pragma("unroll") \
        for(int j4=0;j4<8;j4++) \
          *(float4*)&pf[j4*4]=*(const float4*)&basep[(size_t)row*128+e2b+j4*4]; \
      } \
    }else{ \
      _Pragma("unroll") \
      for(int k=0;k<32;k++) pf[k]=0.f; \
    } \
  }while(0)

  if(grp<ngroups) LIN_LOAD_PF(grp);
  for(;grp<ngroups;grp+=gridDim.x){
    __syncthreads();
    #pragma unroll
    for(int j=0;j<32;j++) inT[(ebase+j)*32+rL]=pf[j];
    __syncthreads();
    int nxt=grp+gridDim.x;
    if(nxt<ngroups) LIN_LOAD_PF(nxt);
    int row0=grp*32;
    int d=t&127,rh=t>>7;
    unsigned long long acc2[8];
    #pragma unroll
    for(int q=0;q<8;q++) acc2[q]=0ull;
    const ulonglong2* I8=(const ulonglong2*)inT;
    #pragma unroll 8
    for(int e=0;e<256;e++){
      float wv=ws[e*128+d];
      unsigned long long wv2=f2pack(wv,wv);
      ulonglong2 u0=I8[e*8+rh*4+0];
      ulonglong2 u1=I8[e*8+rh*4+1];
      ulonglong2 u2=I8[e*8+rh*4+2];
      ulonglong2 u3=I8[e*8+rh*4+3];
      ffma2(acc2[0],wv2,u0.x); ffma2(acc2[1],wv2,u0.y);
      ffma2(acc2[2],wv2,u1.x); ffma2(acc2[3],wv2,u1.y);
      ffma2(acc2[4],wv2,u2.x); ffma2(acc2[5],wv2,u2.y);
      ffma2(acc2[6],wv2,u3.x); ffma2(acc2[7],wv2,u3.y);
    }
    #pragma unroll
    for(int q=0;q<8;q++){
      float lo,hi;
      f2unpack(acc2[q],lo,hi);
      int rlo=row0+rh*16+q*2;
      if(rlo<nrows){
        float v=(cfg==3)?tanhf(lo):fmaxf(lo,0.f);
        outp[(size_t)rlo*128+d]=v;
        if(cfg==2) outmix[(size_t)rlo*128+d]=g_HL[(size_t)rlo*128+d]+v;
      }
      if(rlo+1<nrows){
        float v=(cfg==3)?tanhf(hi):fmaxf(hi,0.f);
        outp[(size_t)(rlo+1)*128+d]=v;
        if(cfg==2) outmix[(size_t)(rlo+1)*128+d]=g_HL[(size_t)(rlo+1)*128+d]+v;
      }
    }
  }
#undef LIN_LOAD_PF
}

// ---------------- ssl ----------------
__global__ void k_ssl(){
  __shared__ float red[128];
  int b=blockIdx.x,t=threadIdx.x;
  int pb=g_PR[b];
  float pos=0.f,neg=0.f;
  for(int l=0;l<50;l++){
    float hl=g_HL[(size_t)b*6400+l*128+t];
    float hg=g_HG[(size_t)b*6400+l*128+t];
    pos+=hl*hg;
    neg+=hg*g_HL[(size_t)pb*6400+g_PC[l]*128+t];
  }
  float sp=1.f/(1.f+expf(-pos)),sn=1.f/(1.f+expf(-neg));
  float term=-logf(1e-8f+sp)-logf(1e-8f+1.f-sn);
  red[t]=term; __syncthreads();
  for(int o=64;o;o>>=1){ if(t<o) red[t]+=red[t+o]; __syncthreads(); }
  if(t==0) g_LP[b]=red[0];
}
__global__ void k_fin(float* __restrict__ out){
  __shared__ float r[128];
  int t=threadIdx.x;
  r[t]=g_LP[t]; __syncthreads();
  for(int o=64;o;o>>=1){ if(t<o) r[t]+=r[t+o]; __syncthreads(); }
  if(t==0) out[819200]=0.005f*r[0];
}

// ---------------- glu/select ----------------
__global__ void __launch_bounds__(256) k_glu(const float* __restrict__ hidden,
    const int* __restrict__ mask,const float* __restrict__ glu1w,
    const float* __restrict__ glu1b,const float* __restrict__ glu2w,
    const float* __restrict__ w2){
  extern __shared__ float sm[];
  float* g1t=sm;        // 16384 [e][d]
  float* hS =sm+16384;  // 6400
  float* nhS=sm+22784;  // 6400
  float* hs =sm+29184;  // 128
  float* t2 =sm+29312;  // 128
  float* bet=sm+29440;  // 64
  float* w2s=sm+29504;  // 128
  float* b1s=sm+29632;  // 128
  int b=blockIdx.x,t=threadIdx.x,warp=t>>5,lane=t&31;
  for(int i=t;i<16384;i+=256){ int e=i>>7,d=i&127; g1t[i]=glu1w[d*128+e]; }
  for(int i=t;i<6400;i+=256){ hS[i]=hidden[(size_t)b*6400+i]; nhS[i]=g_NH[(size_t)b*6400+i]; }
  if(t<128){ w2s[t]=w2[t]; b1s[t]=glu1b[t]; }
  __syncthreads();
  if(t<128){
    float a=0.f,ms=0.f;
    for(int l=0;l<50;l++){ float mv=(float)mask[b*50+l]; a+=hS[l*128+t]*mv; ms+=mv; }
    hs[t]=a/ms;
  }
  __syncthreads();
  if(t<128){
    float a=0.f;
    for(int e=0;e<128;e++) a+=hs[e]*glu2w[t*128+e];
    t2[t]=a;
  }
  __syncthreads();
  const float4* G14=(const float4*)g1t;
  for(int lb=0;lb<56;lb+=8){
    int l=lb+warp;
    if(l<50){
      const float4* N4=(const float4*)(nhS+l*128);
      float a0=0,a1=0,a2=0,a3=0;
      #pragma unroll 4
      for(int e4=0;e4<32;e4++){
        float4 a=N4[e4];
        float4 w=G14[(e4*4+0)*32+lane];
        a0+=a.x*w.x; a1+=a.x*w.y; a2+=a.x*w.z; a3+=a.x*w.w;
        w=G14[(e4*4+1)*32+lane];
        a0+=a.y*w.x; a1+=a.y*w.y; a2+=a.y*w.z; a3+=a.y*w.w;
        w=G14[(e4*4+2)*32+lane];
        a0+=a.z*w.x; a1+=a.z*w.y; a2+=a.z*w.z; a3+=a.z*w.w;
        w=G14[(e4*4+3)*32+lane];
        a0+=a.w*w.x; a1+=a.w*w.y; a2+=a.w*w.z; a3+=a.w*w.w;
      }
      int d0=lane*4;
      a0=1.f/(1.f+expf(-(a0+b1s[d0]+t2[d0])));
      a1=1.f/(1.f+expf(-(a1+b1s[d0+1]+t2[d0+1])));
      a2=1.f/(1.f+expf(-(a2+b1s[d0+2]+t2[d0+2])));
      a3=1.f/(1.f+expf(-(a3+b1s[d0+3]+t2[d0+3])));
      float p=a0*w2s[d0]+a1*w2s[d0+1]+a2*w2s[d0+2]+a3*w2s[d0+3];
      for(int o=16;o;o>>=1) p+=__shfl_xor_sync(0xffffffffu,p,o);
      if(lane==0) bet[l]=p*(float)mask[b*50+l];
    }
  }
  __syncthreads();
  if(t<128){
    float a=0.f;
    for(int l=0;l<50;l++) a+=bet[l]*hS[l*128+t];
    g_SEL[b*128+t]=a;
  }
}

// ---------------- neighbor top-k ----------------
__global__ void __launch_bounds__(128) k_nbr(){
  extern __shared__ float sm[];
  float* sel=sm;  // 16384
  __shared__ float nrm[128];
  __shared__ float ev[128];
  __shared__ float tv[9];
  __shared__ int   ti[9];
  __shared__ float red[4];
  int b=blockIdx.x,t=threadIdx.x;
  for(int i=t;i<16384;i+=128) sel[i]=g_SEL[i];
  __syncthreads();
  { float a=0.f;
    for(int d=0;d<128;d++){ float v=sel[t*128+d]; a+=v*v; }
    nrm[t]=sqrtf(a+128e-6f); }
  __syncthreads();
  float dot=0.f;
  for(int d=0;d<128;d++) dot+=sel[b*128+d]*sel[t*128+d];
  float e=dot/(nrm[b]*nrm[t]);
  float mx=e;
  for(int o=16;o;o>>=1) mx=fmaxf(mx,__shfl_xor_sync(0xffffffffu,mx,o));
  if((t&31)==0) red[t>>5]=mx;
  __syncthreads();
  mx=fmaxf(fmaxf(red[0],red[1]),fmaxf(red[2],red[3]));
  float ex=expf(e-mx);
  float ss=ex;
  for(int o=16;o;o>>=1) ss+=__shfl_xor_sync(0xffffffffu,ss,o);
  __syncthreads();
  if((t&31)==0) red[t>>5]=ss;
  __syncthreads();
  ss=red[0]+red[1]+red[2]+red[3];
  ev[t]=ex/ss;
  __syncthreads();
  if(t==0){
    for(int k=0;k<9;k++){
      float bv=-1.f; int bi=0;
      for(int j=0;j<128;j++) if(ev[j]>bv){ bv=ev[j]; bi=j; }
      tv[k]=bv; ti[k]=bi; ev[bi]=-2.f;
    }
    float m2=tv[0],s2=0.f;
    for(int k=0;k<9;k++){ tv[k]=expf(tv[k]-m2); s2+=tv[k]; }
    float inv=1.f/s2;
    for(int k=0;k<9;k++) tv[k]*=inv;
  }
  __syncthreads();
  float nb=0.f;
  #pragma unroll
  for(int k=0;k<9;k++) nb+=tv[k]*sel[ti[k]*128+t];
  g_SEL2T[t*128+b]=sel[b*128+t]+nb;
}

// ---------------- scores GEMM (FFMA2, 64-j tiles, 2 blocks/SM) --------------
__global__ void __launch_bounds__(256) k_scores(const float* __restrict__ emb,
                                                float* __restrict__ outp){
  extern __shared__ float sm[];
  float* selT=sm;        // 16384 [e][b]
  float* embT=sm+16384;  // 128*65 [e][j]
  int t=threadIdx.x;
  int j0=blockIdx.x*64;
  for(int i=t;i<16384;i+=256) selT[i]=g_SEL2T[i];
  for(int i=t;i<8192;i+=256){
    int j=i&63,e=i>>6;
    int node=1+j0+j;
    embT[e*65+j]=(node<100000)?emb[(size_t)node*128+e]:0.f;
  }
  __syncthreads();
  int j=t&63,bh=(t>>6)&3;
  unsigned long long acc2[16];
  #pragma unroll
  for(int q=0;q<16;q++) acc2[q]=0ull;
  const ulonglong2* S8=(const ulonglong2*)selT;
  #pragma unroll 2
  for(int e=0;e<128;e++){
    float evv=embT[e*65+j];
    unsigned long long ev2=f2pack(evv,evv);
    const ulonglong2* s=&S8[e*32+bh*8];
    #pragma unroll
    for(int q=0;q<8;q++){
      ulonglong2 u=s[q];
      ffma2(acc2[q*2+0],ev2,u.x);
      ffma2(acc2[q*2+1],ev2,u.y);
    }
  }
  if(j0+j<99999){
    #pragma unroll
    for(int q=0;q<16;q++){
      float lo,hi;
      f2unpack(acc2[q],lo,hi);
      int b=bh*32+q*2;
      outp[(size_t)b*99999+j0+j]=lo;
      outp[(size_t)(b+1)*99999+j0+j]=hi;
    }
  }
}

// ---------------- launch (stream-overlapped, capture-fork pattern) ----------
extern "C" void kernel_launch(void* const* d_in,const int* in_sizes,int n_in,
                              void* d_out,int out_size){
  const int*   inputs =(const int*)d_in[0];
  const int*   adj    =(const int*)d_in[1];
  const int*   mask   =(const int*)d_in[2];
  const int*   item   =(const int*)d_in[3];
  const int*   adj_all=(const int*)d_in[5];
  const float* num_w  =(const float*)d_in[6];
  const float* emb    =(const float*)d_in[7];
  const float* pos    =(const float*)d_in[8];
  const float* a_local=(const float*)d_in[9];
  const float* gw1    =(const float*)d_in[10];
  const float* gw2    =(const float*)d_in[11];
  const float* gw3    =(const float*)d_in[12];
  const float* w1     =(const float*)d_in[13];
  const float* w2     =(const float*)d_in[14];
  const float* g1w    =(const float*)d_in[15];
  const float* g1b    =(const float*)d_in[16];
  const float* g2w    =(const float*)d_in[17];
  float* out=(float*)d_out;

  const size_t SM_ATT=24896u*4u;   // 99,584 B -> 2 blocks/SM
  const size_t SM_LIN=40960u*4u;   // 163,840 B -> 1 block/SM
  const size_t SM_GLU=29760u*4u;
  const size_t SM_SC =24704u*4u;   // 98,816 B -> 2 blocks/SM
  const size_t SM_NBR=16384u*4u;
  cudaFuncSetAttribute(k_att2,  cudaFuncAttributeMaxDynamicSharedMemorySize,(int)SM_ATT);
  cudaFuncSetAttribute(k_attm2, cudaFuncAttributeMaxDynamicSharedMemorySize,(int)SM_ATT);
  cudaFuncSetAttribute(k_lin,   cudaFuncAttributeMaxDynamicSharedMemorySize,(int)SM_LIN);
  cudaFuncSetAttribute(k_glu,   cudaFuncAttributeMaxDynamicSharedMemorySize,(int)SM_GLU);
  cudaFuncSetAttribute(k_scores,cudaFuncAttributeMaxDynamicSharedMemorySize,(int)SM_SC);
  cudaFuncSetAttribute(k_nbr,   cudaFuncAttributeMaxDynamicSharedMemorySize,(int)SM_NBR);

  // Lazy one-time stream/event creation (first call is NOT captured: the
  // timed graph contains only kernels + event edges; work is identical
  // on every call).
  static cudaStream_t s1=0;
  static cudaEvent_t evA=0,evB=0,evC=0,evD=0,evE=0;
  if(!s1){
    cudaStreamCreateWithFlags(&s1,cudaStreamNonBlocking);
    cudaEventCreateWithFlags(&evA,cudaEventDisableTiming);
    cudaEventCreateWithFlags(&evB,cudaEventDisableTiming);
    cudaEventCreateWithFlags(&evC,cudaEventDisableTiming);
    cudaEventCreateWithFlags(&evD,cudaEventDisableTiming);
    cudaEventCreateWithFlags(&evE,cudaEventDisableTiming);
  }

  // fork 1: perm + local run under k_att2
  cudaEventRecord(evA,0);
  cudaStreamWaitEvent(s1,evA,0);
  k_perm<<<1,128,0,s1>>>();
  k_local<<<dim3(128,2),256,0,s1>>>(inputs,adj,emb,a_local);

  k_prep1<<<200,256>>>(inputs,adj_all,num_w);
  k_prep2<<<1600,256>>>(adj_all,num_w);
  k_sess<<<128,128>>>(item,mask,emb);
  k_att2<<<296,256,SM_ATT>>>(25,emb,gw1,gw2);                        // -> g_NG0, g_NG1

  // fork 2: cfg0 (reads NG0) runs under cfg1
  cudaEventRecord(evB,0);
  cudaStreamWaitEvent(s1,evB,0);
  k_lin<<<148,256,SM_LIN,s1>>>(6400,0,inputs,emb,0,gw3,0);           // -> g_A0

  k_lin<<<148,256,SM_LIN>>>(51200,1,0,emb,0,gw3,0);                  // -> g_A1
  cudaEventRecord(evC,s1);
  cudaStreamWaitEvent(0,evC,0);      // cfg0 done (it reads g_NG0) before attm2 overwrites NG0; also HL ready
  k_attm2<<<224,256,SM_ATT>>>(4,gw1+129*128,gw2+128);                // -> g_NG0
  k_lin<<<148,256,SM_LIN>>>(6400,2,0,0,0,gw3+256*128,out);           // -> g_HG + out (fused mix)

  // fork 3: ssl + fin run under scores head
  cudaEventRecord(evD,0);
  cudaStreamWaitEvent(s1,evD,0);
  k_ssl<<<128,128,0,s1>>>();
  k_fin<<<1,128,0,s1>>>(out);
  cudaEventRecord(evE,s1);

  k_lin<<<148,256,SM_LIN>>>(6400,3,0,pos,out,w1,0);                  // -> g_NH
  k_glu<<<128,256,SM_GLU>>>(out,mask,g1w,g1b,g2w,w2);
  k_nbr<<<128,128,SM_NBR>>>();
  cudaStreamWaitEvent(0,evE,0);      // join s1 before final kernel (capture completeness)
  k_scores<<<1563,256,SM_SC>>>(emb,out+819201);
}